// round 12
// baseline (speedup 1.0000x reference)
#include <cuda_runtime.h>
#include <cstdint>

typedef uint32_t u32;
#define BB 2048

__device__ float g_scratch[(size_t)BB * 256 * 64];

// ---- smem map (bytes) ----
#define R_H   0
#define R_WV  16384
#define R_WQ  32768
#define R_WT  49152
#define R_K   65536      // K tiles hi/lo (64KB)
#define R_V   131072     // V tile hi only (32KB)
#define R_WKP 163840     // Wk hi/lo (16KB)
#define R_KM  180224     // 16 floats: per-warp max ||k||^2
#define SMEM_BYTES 180288
#define LOD_T 32768
#define LOD_W 8192

static __device__ __forceinline__ u32 s2u(const void* p) {
    u32 a;
    asm("{ .reg .u64 t; cvta.to.shared.u64 t, %1; cvt.u32.u64 %0, t; }" : "=r"(a) : "l"(p));
    return a;
}
static __device__ __forceinline__ u32 swz(u32 o) { return o ^ ((o >> 3) & 0x70); }

static __device__ __forceinline__ void ldm4(u32* r, u32 a) {
    asm volatile("ldmatrix.sync.aligned.m8n8.x4.shared.b16 {%0,%1,%2,%3},[%4];"
                 : "=r"(r[0]), "=r"(r[1]), "=r"(r[2]), "=r"(r[3]) : "r"(a));
}
static __device__ __forceinline__ void ldm2(u32* r, u32 a) {
    asm volatile("ldmatrix.sync.aligned.m8n8.x2.shared.b16 {%0,%1},[%2];"
                 : "=r"(r[0]), "=r"(r[1]) : "r"(a));
}
static __device__ __forceinline__ void ldm2t(u32* r, u32 a) {
    asm volatile("ldmatrix.sync.aligned.m8n8.x2.trans.shared.b16 {%0,%1},[%2];"
                 : "=r"(r[0]), "=r"(r[1]) : "r"(a));
}
static __device__ __forceinline__ void hmma(float* c, const u32* a, const u32* b) {
    asm volatile("mma.sync.aligned.m16n8k16.row.col.f32.f16.f16.f32 "
                 "{%0,%1,%2,%3},{%4,%5,%6,%7},{%8,%9},{%0,%1,%2,%3};"
                 : "+f"(c[0]), "+f"(c[1]), "+f"(c[2]), "+f"(c[3])
                 : "r"(a[0]), "r"(a[1]), "r"(a[2]), "r"(a[3]), "r"(b[0]), "r"(b[1]));
}
static __device__ __forceinline__ u32 f16pk(float a, float b) {   // a -> low half
    u32 r; asm("cvt.rn.f16x2.f32 %0,%1,%2;" : "=r"(r) : "f"(b), "f"(a)); return r;
}
static __device__ __forceinline__ void h2up(u32 h, float& a, float& b) {
    asm("{.reg .b16 l,hh; mov.b32 {l,hh},%2; cvt.f32.f16 %0,l; cvt.f32.f16 %1,hh;}"
        : "=f"(a), "=f"(b) : "r"(h));
}
static __device__ __forceinline__ void split2(float a, float b, u32& hi, u32& lo) {
    u32 h = f16pk(a, b); float fa, fb; h2up(h, fa, fb);
    hi = h; lo = f16pk(a - fa, b - fb);
}
static __device__ __forceinline__ void st32(u32 a, u32 v) {
    asm volatile("st.shared.b32 [%0],%1;" :: "r"(a), "r"(v) : "memory");
}

// 3-term 64-col GEMM (paired-n interleave, batched LDSM).
static __device__ __forceinline__ void gemm64(float (*c)[4],
        const u32 (*ah)[4], const u32 (*al)[4],
        u32 bbase, u32 lod, int n0, int k0, int ll) {
#pragma unroll
    for (int np = 0; np < 4; np++) {
#pragma unroll
        for (int k = 0; k < 4; k++) {
            u32 offA = (u32)(n0 + 16 * np + (ll & 7)) * 128 + (u32)(k0 + 16 * k) * 2 + ((ll >> 3) & 1) * 16;
            u32 offB = offA + 8 * 128;
            u32 aA = bbase + swz(offA), aB = bbase + swz(offB);
            u32 bhA[2], blA[2], bhB[2], blB[2];
            ldm2(bhA, aA); ldm2(bhB, aB); ldm2(blA, aA + lod); ldm2(blB, aB + lod);
            hmma(c[2 * np], ah[k], bhA); hmma(c[2 * np + 1], ah[k], bhB);
            hmma(c[2 * np], ah[k], blA); hmma(c[2 * np + 1], ah[k], blB);
            hmma(c[2 * np], al[k], bhA); hmma(c[2 * np + 1], al[k], bhB);
        }
    }
}
// 2-term variant: A hi only, B hi+lo.
static __device__ __forceinline__ void gemm64_2(float (*c)[4],
        const u32 (*ah)[4], u32 bbase, u32 lod, int n0, int k0, int ll) {
#pragma unroll
    for (int np = 0; np < 4; np++) {
#pragma unroll
        for (int k = 0; k < 4; k++) {
            u32 offA = (u32)(n0 + 16 * np + (ll & 7)) * 128 + (u32)(k0 + 16 * k) * 2 + ((ll >> 3) & 1) * 16;
            u32 offB = offA + 8 * 128;
            u32 aA = bbase + swz(offA), aB = bbase + swz(offB);
            u32 bhA[2], blA[2], bhB[2], blB[2];
            ldm2(bhA, aA); ldm2(bhB, aB); ldm2(blA, aA + lod); ldm2(blB, aB + lod);
            hmma(c[2 * np], ah[k], bhA); hmma(c[2 * np + 1], ah[k], bhB);
            hmma(c[2 * np], ah[k], blA); hmma(c[2 * np + 1], ah[k], blB);
        }
    }
}
// 1-term trans variant: A hi, B hi (AV).
static __device__ __forceinline__ void gemm64_1t(float (*c)[4],
        const u32 (*ah)[4], u32 bbase, int k0, int ll) {
#pragma unroll
    for (int np = 0; np < 4; np++) {
#pragma unroll
        for (int k = 0; k < 4; k++) {
            u32 offA = (u32)(k0 + 16 * k + ((ll >> 3) & 1) * 8 + (ll & 7)) * 128 + (u32)(32 * np);
            u32 offB = offA + 16;
            u32 bhA[2], bhB[2];
            ldm2t(bhA, bbase + swz(offA)); ldm2t(bhB, bbase + swz(offB));
            hmma(c[2 * np], ah[k], bhA); hmma(c[2 * np + 1], ah[k], bhB);
        }
    }
}
static __device__ __forceinline__ void c2a(const float (*c)[4], u32 (*fh)[4], u32 (*fl)[4]) {
#pragma unroll
    for (int kk = 0; kk < 4; kk++) {
        split2(c[2 * kk][0],     c[2 * kk][1],     fh[kk][0], fl[kk][0]);
        split2(c[2 * kk][2],     c[2 * kk][3],     fh[kk][1], fl[kk][1]);
        split2(c[2 * kk + 1][0], c[2 * kk + 1][1], fh[kk][2], fl[kk][2]);
        split2(c[2 * kk + 1][2], c[2 * kk + 1][3], fh[kk][3], fl[kk][3]);
    }
}
static __device__ __forceinline__ void c2a_hi(const float (*c)[4], u32 (*fh)[4]) {
#pragma unroll
    for (int kk = 0; kk < 4; kk++) {
        fh[kk][0] = f16pk(c[2 * kk][0],     c[2 * kk][1]);
        fh[kk][1] = f16pk(c[2 * kk][2],     c[2 * kk][3]);
        fh[kk][2] = f16pk(c[2 * kk + 1][0], c[2 * kk + 1][1]);
        fh[kk][3] = f16pk(c[2 * kk + 1][2], c[2 * kk + 1][3]);
    }
}
static __device__ __forceinline__ void addbias(float (*c)[4], const float* __restrict__ bias, int q4) {
#pragma unroll
    for (int n = 0; n < 8; n++) {
        float b0 = bias[8 * n + 2 * q4], b1 = bias[8 * n + 2 * q4 + 1];
        c[n][0] += b0; c[n][1] += b1; c[n][2] += b0; c[n][3] += b1;
    }
}
static __device__ __forceinline__ void cstore16(const float (*c)[4], u32 base, int m0, int lane) {
    int g = lane >> 2, q4 = lane & 3;
#pragma unroll
    for (int n = 0; n < 8; n++) {
        u32 o0 = swz((u32)(m0 + g) * 128 + 16 * n + 4 * q4);
        u32 o1 = swz((u32)(m0 + g + 8) * 128 + 16 * n + 4 * q4);
        u32 h0, l0, h1, l1;
        split2(c[n][0], c[n][1], h0, l0);
        split2(c[n][2], c[n][3], h1, l1);
        st32(base + o0, h0); st32(base + LOD_T + o0, l0);
        st32(base + o1, h1); st32(base + LOD_T + o1, l1);
    }
}
static __device__ __forceinline__ void cstore16_hi(const float (*c)[4], u32 base, int m0, int lane) {
    int g = lane >> 2, q4 = lane & 3;
#pragma unroll
    for (int n = 0; n < 8; n++) {
        u32 o0 = swz((u32)(m0 + g) * 128 + 16 * n + 4 * q4);
        u32 o1 = swz((u32)(m0 + g + 8) * 128 + 16 * n + 4 * q4);
        st32(base + o0, f16pk(c[n][0], c[n][1]));
        st32(base + o1, f16pk(c[n][2], c[n][3]));
    }
}
static __device__ __forceinline__ void rowsum(const float (*c)[4], float& r0, float& r1) {
    float s0 = 0.f, s1 = 0.f;
#pragma unroll
    for (int n = 0; n < 8; n++) { s0 += c[n][0] + c[n][1]; s1 += c[n][2] + c[n][3]; }
    s0 += __shfl_xor_sync(~0u, s0, 1); s0 += __shfl_xor_sync(~0u, s0, 2);
    s1 += __shfl_xor_sync(~0u, s1, 1); s1 += __shfl_xor_sync(~0u, s1, 2);
    r0 = s0; r1 = s1;
}
static __device__ __forceinline__ void rowsumsq(const float (*c)[4], float& r0, float& r1) {
    float s0 = 0.f, s1 = 0.f;
#pragma unroll
    for (int n = 0; n < 8; n++) {
        s0 += c[n][0] * c[n][0] + c[n][1] * c[n][1];
        s1 += c[n][2] * c[n][2] + c[n][3] * c[n][3];
    }
    s0 += __shfl_xor_sync(~0u, s0, 1); s0 += __shfl_xor_sync(~0u, s0, 2);
    s1 += __shfl_xor_sync(~0u, s1, 1); s1 += __shfl_xor_sync(~0u, s1, 2);
    r0 = s0; r1 = s1;
}
static __device__ __forceinline__ void stageW(const float* __restrict__ W, u32 base, int tid) {
    for (int i = tid; i < 2048; i += 512) {
        int r = i >> 5, c2 = (i & 31) * 2;
        float2 w = *(const float2*)(W + r * 64 + c2);
        u32 h, l; split2(w.x, w.y, h, l);
        u32 o = swz((u32)r * 128 + (u32)c2 * 2);
        st32(base + o, h); st32(base + LOD_W + o, l);
    }
}

// ---------------- transposes (float4, 128-wide t tiles; chunked by n) ----------------
__global__ void k_tin(const float* __restrict__ in, int n0) {
    __shared__ float tile[32][129];
    int n = n0 + (blockIdx.z >> 8), f = blockIdx.z & 255;
    int c0 = blockIdx.y << 5, t0 = blockIdx.x << 7;
    int j = threadIdx.x;
    int tr = j & 31, cr = j >> 5;
    size_t base_in = ((size_t)(n * 64 + c0) * 256 + f) * 256 + t0;
#pragma unroll
    for (int p = 0; p < 4; p++) {
        int c = cr + p * 8;
        float4 v = *(const float4*)(in + base_in + (size_t)c * 65536 + 4 * tr);
        tile[c][4 * tr] = v.x; tile[c][4 * tr + 1] = v.y;
        tile[c][4 * tr + 2] = v.z; tile[c][4 * tr + 3] = v.w;
    }
    __syncthreads();
    int cw = (j & 7) * 4, trw = j >> 3;
    size_t base_out = (size_t)(n * 256) * 16384 + (size_t)f * 64 + c0;
#pragma unroll
    for (int p = 0; p < 4; p++) {
        int t = trw + p * 32;
        float4 v = make_float4(tile[cw][t], tile[cw + 1][t], tile[cw + 2][t], tile[cw + 3][t]);
        *(float4*)(g_scratch + base_out + (size_t)(t0 + t) * 16384 + cw) = v;
    }
}
__global__ void k_tout(const float* __restrict__ in, float* __restrict__ out, int n0) {
    __shared__ float tile[32][129];
    int n = n0 + (blockIdx.z >> 8), f = blockIdx.z & 255;
    int c0 = blockIdx.y << 5, t0 = blockIdx.x << 7;
    int j = threadIdx.x;
    int cw = (j & 7) * 4, trw = j >> 3;
    size_t base_y = (size_t)(n * 256) * 16384 + (size_t)f * 64 + c0;
#pragma unroll
    for (int p = 0; p < 4; p++) {
        int t = trw + p * 32;
        float4 v = *(const float4*)(g_scratch + base_y + (size_t)(t0 + t) * 16384 + cw);
        tile[cw][t] = v.x; tile[cw + 1][t] = v.y; tile[cw + 2][t] = v.z; tile[cw + 3][t] = v.w;
    }
    __syncthreads();
    int tr = j & 31, cr = j >> 5;
    size_t base_o = ((size_t)(n * 64 + c0) * 256 + f) * 256 + t0;
#pragma unroll
    for (int p = 0; p < 4; p++) {
        int c = cr + p * 8;
        size_t a = base_o + (size_t)c * 65536 + 4 * tr;
        float4 r = *(const float4*)(in + a);
        r.x += tile[c][4 * tr];     r.y += tile[c][4 * tr + 1];
        r.z += tile[c][4 * tr + 2]; r.w += tile[c][4 * tr + 3];
        *(float4*)(out + a) = r;
    }
}

// ---------------- fused attention (mma.sync, 512 threads, 16 rows/warp) ----------------
__global__ void __launch_bounds__(512, 1) k_attn(
    const float* __restrict__ Wq, const float* __restrict__ bq,
    const float* __restrict__ Wk, const float* __restrict__ bk,
    const float* __restrict__ Wv, const float* __restrict__ bv,
    const float* __restrict__ g1, const float* __restrict__ b1,
    const float* __restrict__ g2, const float* __restrict__ b2,
    const float* __restrict__ Wt, const float* __restrict__ bt,
    const float* __restrict__ g3, const float* __restrict__ b3,
    const float* __restrict__ alpha, int b0)
{
    extern __shared__ char smem[];
    u32 sb = s2u(smem);
    float* wkm = (float*)(smem + R_KM);
    int tid = threadIdx.x, lane = tid & 31, wrp = tid >> 5;
    int g = lane >> 2, q4 = lane & 3, ll = lane & 15;
    int m0 = wrp * 16;
    float* xb = g_scratch + (size_t)(blockIdx.x + b0) * 16384;

    // Stage Wk (overlaps LN1's x loads)
    stageW(Wk, sb + R_WKP, tid);

    // Phase 0: LN1 (warp per row, 16 warps) -> H hi/lo tiles
    {
        float2 g1v = ((const float2*)g1)[lane];
        float2 b1v = ((const float2*)b1)[lane];
        for (int r = wrp; r < 256; r += 16) {
            float2 x = *(const float2*)(xb + r * 64 + 2 * lane);
            float s = x.x + x.y;
#pragma unroll
            for (int o = 16; o; o >>= 1) s += __shfl_xor_sync(~0u, s, o);
            float mean = s * (1.0f / 64.0f);
            float d0 = x.x - mean, d1 = x.y - mean;
            float v = d0 * d0 + d1 * d1;
#pragma unroll
            for (int o = 16; o; o >>= 1) v += __shfl_xor_sync(~0u, v, o);
            float rs = rsqrtf(v * (1.0f / 64.0f) + 1e-5f);
            u32 h, l; split2(d0 * rs * g1v.x + b1v.x, d1 * rs * g1v.y + b1v.y, h, l);
            u32 o = swz((u32)r * 128 + (u32)lane * 4);
            st32(sb + R_H + o, h); st32(sb + R_H + LOD_T + o, l);
        }
    }
    __syncthreads();

    // H A-fragments for this warp's 16 rows
    u32 hah[4][4], hal[4][4];
#pragma unroll
    for (int k = 0; k < 4; k++) {
        u32 o = swz((u32)(m0 + (lane & 15)) * 128 + (u32)k * 32 + ((lane >> 4) & 1) * 16);
        ldm4(hah[k], sb + R_H + o);
        ldm4(hal[k], sb + R_H + LOD_T + o);
    }
    __syncthreads();   // H tiles consumed -> region becomes weight storage

    // Prefetch Wv/Wq/Wt into registers (latency hidden behind K projection)
    float2 wv_r[4], wq_r[4], wt_r[4];
#pragma unroll
    for (int it = 0; it < 4; it++) {
        int i = tid + it * 512;
        int r = i >> 5, c2 = (i & 31) * 2;
        wv_r[it] = *(const float2*)(Wv + r * 64 + c2);
        wq_r[it] = *(const float2*)(Wq + r * 64 + c2);
        wt_r[it] = *(const float2*)(Wt + r * 64 + c2);
    }

    // K projection (Wk preloaded) -> K tiles + max||k||^2
    {
        float c[8][4];
#pragma unroll
        for (int n = 0; n < 8; n++) { c[n][0] = c[n][1] = c[n][2] = c[n][3] = 0.f; }
        gemm64(c, hah, hal, sb + R_WKP, LOD_W, 0, 0, ll);
        addbias(c, bk, q4);
        float a0, a1; rowsumsq(c, a0, a1);
        float kmx = fmaxf(a0, a1);
#pragma unroll
        for (int o = 16; o; o >>= 1) kmx = fmaxf(kmx, __shfl_xor_sync(~0u, kmx, o));
        if (lane == 0) wkm[wrp] = kmx;
        cstore16(c, sb + R_K, m0, lane);
    }
    // Store prefetched weights into the dead H region
#pragma unroll
    for (int it = 0; it < 4; it++) {
        int i = tid + it * 512;
        int r = i >> 5, c2 = (i & 31) * 2;
        u32 o = swz((u32)r * 128 + (u32)c2 * 2);
        u32 h, l;
        split2(wv_r[it].x, wv_r[it].y, h, l); st32(sb + R_WV + o, h); st32(sb + R_WV + LOD_W + o, l);
        split2(wq_r[it].x, wq_r[it].y, h, l); st32(sb + R_WQ + o, h); st32(sb + R_WQ + LOD_W + o, l);
        split2(wt_r[it].x, wt_r[it].y, h, l); st32(sb + R_WT + o, h); st32(sb + R_WT + LOD_W + o, l);
    }
    __syncthreads();

    // V projection -> V tile (hi only; 2-term suffices since v is f16-rounded anyway)
    {
        float c[8][4];
#pragma unroll
        for (int n = 0; n < 8; n++) { c[n][0] = c[n][1] = c[n][2] = c[n][3] = 0.f; }
        gemm64_2(c, hah, sb + R_WV, LOD_W, 0, 0, ll);
        addbias(c, bv, q4);
        cstore16_hi(c, sb + R_V, m0, lane);
    }
    // Q projection -> A-fragments + ||q||
    u32 qah[4][4], qal[4][4];
    float qn0, qn1;
    {
        float c[8][4];
#pragma unroll
        for (int n = 0; n < 8; n++) { c[n][0] = c[n][1] = c[n][2] = c[n][3] = 0.f; }
        gemm64(c, hah, hal, sb + R_WQ, LOD_W, 0, 0, ll);
        addbias(c, bq, q4);
        float a0, a1; rowsumsq(c, a0, a1);
        qn0 = sqrtf(a0); qn1 = sqrtf(a1);
        c2a(c, qah, qal);
    }
    __syncthreads();   // K, V tiles + wkm complete

    float kmax;
    {
        float m = wkm[0];
#pragma unroll
        for (int i = 1; i < 16; i++) m = fmaxf(m, wkm[i]);
        kmax = sqrtf(m);
    }
    // Flash loop (sync-free): safe max = ||q||*kmax/8 - 8
    float mr0 = qn0 * kmax * 0.125f - 8.0f;
    float mr1 = qn1 * kmax * 0.125f - 8.0f;
    float ov[8][4];
#pragma unroll
    for (int n = 0; n < 8; n++) { ov[n][0] = ov[n][1] = ov[n][2] = ov[n][3] = 0.f; }

#pragma unroll 1
    for (int sc = 0; sc < 4; sc++) {
        float s[8][4];
#pragma unroll
        for (int n = 0; n < 8; n++) { s[n][0] = s[n][1] = s[n][2] = s[n][3] = 0.f; }
        gemm64(s, qah, qal, sb + R_K, LOD_T, sc * 64, 0, ll);
#pragma unroll
        for (int n = 0; n < 8; n++) {
            s[n][0] = __expf(fmaf(s[n][0], 0.125f, -mr0));
            s[n][1] = __expf(fmaf(s[n][1], 0.125f, -mr0));
            s[n][2] = __expf(fmaf(s[n][2], 0.125f, -mr1));
            s[n][3] = __expf(fmaf(s[n][3], 0.125f, -mr1));
        }
        u32 ph[4][4];
        c2a_hi(s, ph);
        gemm64_1t(ov, ph, sb + R_V, sc * 64, ll);
    }

    // Epilogue: LN2 (regs) -> Wt GEMM (2-term) -> LN3 + PReLU -> scratch (coalesced)
    float alv = __ldg(alpha);
    {
        float s0v, s1v, ss0, ss1;
        rowsum(ov, s0v, s1v);
        rowsumsq(ov, ss0, ss1);
        float mu0 = s0v * (1.0f / 64.0f), mu1 = s1v * (1.0f / 64.0f);
        float rs0 = rsqrtf(fmaxf(ss0 * (1.0f / 64.0f) - mu0 * mu0, 0.f) + 1e-12f);
        float rs1 = rsqrtf(fmaxf(ss1 * (1.0f / 64.0f) - mu1 * mu1, 0.f) + 1e-12f);
#pragma unroll
        for (int n = 0; n < 8; n++) {
            int c0i = 8 * n + 2 * q4;
            float2 g2v = *(const float2*)(g2 + c0i);
            float2 b2v = *(const float2*)(b2 + c0i);
            ov[n][0] = (ov[n][0] - mu0) * rs0 * g2v.x + b2v.x;
            ov[n][1] = (ov[n][1] - mu0) * rs0 * g2v.y + b2v.y;
            ov[n][2] = (ov[n][2] - mu1) * rs1 * g2v.x + b2v.x;
            ov[n][3] = (ov[n][3] - mu1) * rs1 * g2v.y + b2v.y;
        }
    }
    {
        u32 yh[4][4];
        c2a_hi(ov, yh);
        float y[8][4];
#pragma unroll
        for (int n = 0; n < 8; n++) { y[n][0] = y[n][1] = y[n][2] = y[n][3] = 0.f; }
        gemm64_2(y, yh, sb + R_WT, LOD_W, 0, 0, ll);
        addbias(y, bt, q4);
        float s0v, s1v, ss0, ss1;
        rowsum(y, s0v, s1v);
        rowsumsq(y, ss0, ss1);
        float mu0 = s0v * (1.0f / 64.0f), mu1 = s1v * (1.0f / 64.0f);
        float rs0 = rsqrtf(ss0 * (1.0f / 64.0f) - mu0 * mu0 + 1e-5f);
        float rs1 = rsqrtf(ss1 * (1.0f / 64.0f) - mu1 * mu1 + 1e-5f);
#pragma unroll
        for (int n = 0; n < 8; n++) {
            int c0i = 8 * n + 2 * q4;
            float2 g3v = *(const float2*)(g3 + c0i);
            float2 b3v = *(const float2*)(b3 + c0i);
            float e0 = (y[n][0] - mu0) * rs0 * g3v.x + b3v.x; e0 = e0 >= 0.f ? e0 : alv * e0;
            float e1 = (y[n][1] - mu0) * rs0 * g3v.y + b3v.y; e1 = e1 >= 0.f ? e1 : alv * e1;
            float e2 = (y[n][2] - mu1) * rs1 * g3v.x + b3v.x; e2 = e2 >= 0.f ? e2 : alv * e2;
            float e3 = (y[n][3] - mu1) * rs1 * g3v.y + b3v.y; e3 = e3 >= 0.f ? e3 : alv * e3;
            *(float2*)(xb + (m0 + g) * 64 + c0i)     = make_float2(e0, e1);
            *(float2*)(xb + (m0 + g + 8) * 64 + c0i) = make_float2(e2, e3);
        }
    }
}

// ---------------- launch: 4-chunk pipeline (tin || attn || tout) ----------------
#define NCHUNK 4
extern "C" void kernel_launch(void* const* d_in, const int* in_sizes, int n_in,
                              void* d_out, int out_size) {
    (void)in_sizes; (void)n_in; (void)out_size;
    const float* inputs = (const float*)d_in[0];
    const float* Wq = (const float*)d_in[1];  const float* bq = (const float*)d_in[2];
    const float* Wk = (const float*)d_in[3];  const float* bk = (const float*)d_in[4];
    const float* Wv = (const float*)d_in[5];  const float* bv = (const float*)d_in[6];
    const float* g1 = (const float*)d_in[7];  const float* b1 = (const float*)d_in[8];
    const float* g2 = (const float*)d_in[9];  const float* b2 = (const float*)d_in[10];
    const float* Wt = (const float*)d_in[11]; const float* bt = (const float*)d_in[12];
    const float* g3 = (const float*)d_in[13]; const float* b3 = (const float*)d_in[14];
    const float* alpha = (const float*)d_in[15];
    float* out = (float*)d_out;

    static cudaStream_t sA = nullptr, sB = nullptr;
    static cudaEvent_t evT[NCHUNK], evA[NCHUNK], evRoot, evEnd;
    if (!sA) {   // first call is the (uncaptured) correctness run
        cudaStreamCreateWithFlags(&sA, cudaStreamNonBlocking);
        cudaStreamCreateWithFlags(&sB, cudaStreamNonBlocking);
        for (int i = 0; i < NCHUNK; i++) {
            cudaEventCreateWithFlags(&evT[i], cudaEventDisableTiming);
            cudaEventCreateWithFlags(&evA[i], cudaEventDisableTiming);
        }
        cudaEventCreateWithFlags(&evRoot, cudaEventDisableTiming);
        cudaEventCreateWithFlags(&evEnd, cudaEventDisableTiming);
        cudaFuncSetAttribute(k_attn, cudaFuncAttributeMaxDynamicSharedMemorySize, SMEM_BYTES);
    }

    dim3 tg(2, 2, 512);          // per-chunk transpose grid (2 n-values)
    cudaEventRecord(evRoot, 0);
    cudaStreamWaitEvent(sA, evRoot, 0);
    for (int g = 0; g < NCHUNK; g++) {
        k_tin<<<tg, 256, 0, sA>>>(inputs, 2 * g);
        cudaEventRecord(evT[g], sA);
    }
    for (int g = 0; g < NCHUNK; g++) {
        cudaStreamWaitEvent(0, evT[g], 0);
        k_attn<<<512, 512, SMEM_BYTES>>>(Wq, bq, Wk, bk, Wv, bv, g1, b1, g2, b2,
                                         Wt, bt, g3, b3, alpha, 512 * g);
        cudaEventRecord(evA[g], 0);
        cudaStreamWaitEvent(sB, evA[g], 0);
        k_tout<<<tg, 256, 0, sB>>>(inputs, out, 2 * g);
    }
    cudaEventRecord(evEnd, sB);
    cudaStreamWaitEvent(0, evEnd, 0);
}

// round 13
// speedup vs baseline: 1.0878x; 1.0878x over previous
#include <cuda_runtime.h>
#include <cstdint>

typedef uint32_t u32;
#define BB 2048

__device__ float g_scratch[(size_t)BB * 256 * 64];

// ---- smem map (bytes) ----
#define R_H   0
#define R_WV  16384
#define R_WQ  32768
#define R_WT  49152
#define R_K   65536      // K tiles hi/lo (64KB)
#define R_V   131072     // V tile hi only (32KB)
#define R_WKP 163840     // Wk hi/lo (16KB)
#define R_KM  180224     // 16 floats: per-warp max ||k||^2
#define SMEM_BYTES 180288
#define LOD_T 32768
#define LOD_W 8192

static __device__ __forceinline__ u32 s2u(const void* p) {
    u32 a;
    asm("{ .reg .u64 t; cvta.to.shared.u64 t, %1; cvt.u32.u64 %0, t; }" : "=r"(a) : "l"(p));
    return a;
}
static __device__ __forceinline__ u32 swz(u32 o) { return o ^ ((o >> 3) & 0x70); }

static __device__ __forceinline__ void ldm4(u32* r, u32 a) {
    asm volatile("ldmatrix.sync.aligned.m8n8.x4.shared.b16 {%0,%1,%2,%3},[%4];"
                 : "=r"(r[0]), "=r"(r[1]), "=r"(r[2]), "=r"(r[3]) : "r"(a));
}
static __device__ __forceinline__ void ldm2(u32* r, u32 a) {
    asm volatile("ldmatrix.sync.aligned.m8n8.x2.shared.b16 {%0,%1},[%2];"
                 : "=r"(r[0]), "=r"(r[1]) : "r"(a));
}
static __device__ __forceinline__ void ldm2t(u32* r, u32 a) {
    asm volatile("ldmatrix.sync.aligned.m8n8.x2.trans.shared.b16 {%0,%1},[%2];"
                 : "=r"(r[0]), "=r"(r[1]) : "r"(a));
}
static __device__ __forceinline__ void hmma(float* c, const u32* a, const u32* b) {
    asm volatile("mma.sync.aligned.m16n8k16.row.col.f32.f16.f16.f32 "
                 "{%0,%1,%2,%3},{%4,%5,%6,%7},{%8,%9},{%0,%1,%2,%3};"
                 : "+f"(c[0]), "+f"(c[1]), "+f"(c[2]), "+f"(c[3])
                 : "r"(a[0]), "r"(a[1]), "r"(a[2]), "r"(a[3]), "r"(b[0]), "r"(b[1]));
}
static __device__ __forceinline__ u32 f16pk(float a, float b) {   // a -> low half
    u32 r; asm("cvt.rn.f16x2.f32 %0,%1,%2;" : "=r"(r) : "f"(b), "f"(a)); return r;
}
static __device__ __forceinline__ void h2up(u32 h, float& a, float& b) {
    asm("{.reg .b16 l,hh; mov.b32 {l,hh},%2; cvt.f32.f16 %0,l; cvt.f32.f16 %1,hh;}"
        : "=f"(a), "=f"(b) : "r"(h));
}
static __device__ __forceinline__ void split2(float a, float b, u32& hi, u32& lo) {
    u32 h = f16pk(a, b); float fa, fb; h2up(h, fa, fb);
    hi = h; lo = f16pk(a - fa, b - fb);
}
static __device__ __forceinline__ void st32(u32 a, u32 v) {
    asm volatile("st.shared.b32 [%0],%1;" :: "r"(a), "r"(v) : "memory");
}

// 3-term 64-col GEMM (paired-n interleave, batched LDSM).
static __device__ __forceinline__ void gemm64(float (*c)[4],
        const u32 (*ah)[4], const u32 (*al)[4],
        u32 bbase, u32 lod, int n0, int k0, int ll) {
#pragma unroll
    for (int np = 0; np < 4; np++) {
#pragma unroll
        for (int k = 0; k < 4; k++) {
            u32 offA = (u32)(n0 + 16 * np + (ll & 7)) * 128 + (u32)(k0 + 16 * k) * 2 + ((ll >> 3) & 1) * 16;
            u32 offB = offA + 8 * 128;
            u32 aA = bbase + swz(offA), aB = bbase + swz(offB);
            u32 bhA[2], blA[2], bhB[2], blB[2];
            ldm2(bhA, aA); ldm2(bhB, aB); ldm2(blA, aA + lod); ldm2(blB, aB + lod);
            hmma(c[2 * np], ah[k], bhA); hmma(c[2 * np + 1], ah[k], bhB);
            hmma(c[2 * np], ah[k], blA); hmma(c[2 * np + 1], ah[k], blB);
            hmma(c[2 * np], al[k], bhA); hmma(c[2 * np + 1], al[k], bhB);
        }
    }
}
// 2-term variant: A hi only, B hi+lo.
static __device__ __forceinline__ void gemm64_2(float (*c)[4],
        const u32 (*ah)[4], u32 bbase, u32 lod, int n0, int k0, int ll) {
#pragma unroll
    for (int np = 0; np < 4; np++) {
#pragma unroll
        for (int k = 0; k < 4; k++) {
            u32 offA = (u32)(n0 + 16 * np + (ll & 7)) * 128 + (u32)(k0 + 16 * k) * 2 + ((ll >> 3) & 1) * 16;
            u32 offB = offA + 8 * 128;
            u32 aA = bbase + swz(offA), aB = bbase + swz(offB);
            u32 bhA[2], blA[2], bhB[2], blB[2];
            ldm2(bhA, aA); ldm2(bhB, aB); ldm2(blA, aA + lod); ldm2(blB, aB + lod);
            hmma(c[2 * np], ah[k], bhA); hmma(c[2 * np + 1], ah[k], bhB);
            hmma(c[2 * np], ah[k], blA); hmma(c[2 * np + 1], ah[k], blB);
        }
    }
}
// 1-term trans variant: A hi, B hi (AV).
static __device__ __forceinline__ void gemm64_1t(float (*c)[4],
        const u32 (*ah)[4], u32 bbase, int k0, int ll) {
#pragma unroll
    for (int np = 0; np < 4; np++) {
#pragma unroll
        for (int k = 0; k < 4; k++) {
            u32 offA = (u32)(k0 + 16 * k + ((ll >> 3) & 1) * 8 + (ll & 7)) * 128 + (u32)(32 * np);
            u32 offB = offA + 16;
            u32 bhA[2], bhB[2];
            ldm2t(bhA, bbase + swz(offA)); ldm2t(bhB, bbase + swz(offB));
            hmma(c[2 * np], ah[k], bhA); hmma(c[2 * np + 1], ah[k], bhB);
        }
    }
}
static __device__ __forceinline__ void c2a(const float (*c)[4], u32 (*fh)[4], u32 (*fl)[4]) {
#pragma unroll
    for (int kk = 0; kk < 4; kk++) {
        split2(c[2 * kk][0],     c[2 * kk][1],     fh[kk][0], fl[kk][0]);
        split2(c[2 * kk][2],     c[2 * kk][3],     fh[kk][1], fl[kk][1]);
        split2(c[2 * kk + 1][0], c[2 * kk + 1][1], fh[kk][2], fl[kk][2]);
        split2(c[2 * kk + 1][2], c[2 * kk + 1][3], fh[kk][3], fl[kk][3]);
    }
}
static __device__ __forceinline__ void c2a_hi(const float (*c)[4], u32 (*fh)[4]) {
#pragma unroll
    for (int kk = 0; kk < 4; kk++) {
        fh[kk][0] = f16pk(c[2 * kk][0],     c[2 * kk][1]);
        fh[kk][1] = f16pk(c[2 * kk][2],     c[2 * kk][3]);
        fh[kk][2] = f16pk(c[2 * kk + 1][0], c[2 * kk + 1][1]);
        fh[kk][3] = f16pk(c[2 * kk + 1][2], c[2 * kk + 1][3]);
    }
}
static __device__ __forceinline__ void addbias(float (*c)[4], const float* __restrict__ bias, int q4) {
#pragma unroll
    for (int n = 0; n < 8; n++) {
        float b0 = bias[8 * n + 2 * q4], b1 = bias[8 * n + 2 * q4 + 1];
        c[n][0] += b0; c[n][1] += b1; c[n][2] += b0; c[n][3] += b1;
    }
}
static __device__ __forceinline__ void cstore16(const float (*c)[4], u32 base, int m0, int lane) {
    int g = lane >> 2, q4 = lane & 3;
#pragma unroll
    for (int n = 0; n < 8; n++) {
        u32 o0 = swz((u32)(m0 + g) * 128 + 16 * n + 4 * q4);
        u32 o1 = swz((u32)(m0 + g + 8) * 128 + 16 * n + 4 * q4);
        u32 h0, l0, h1, l1;
        split2(c[n][0], c[n][1], h0, l0);
        split2(c[n][2], c[n][3], h1, l1);
        st32(base + o0, h0); st32(base + LOD_T + o0, l0);
        st32(base + o1, h1); st32(base + LOD_T + o1, l1);
    }
}
static __device__ __forceinline__ void cstore16_hi(const float (*c)[4], u32 base, int m0, int lane) {
    int g = lane >> 2, q4 = lane & 3;
#pragma unroll
    for (int n = 0; n < 8; n++) {
        u32 o0 = swz((u32)(m0 + g) * 128 + 16 * n + 4 * q4);
        u32 o1 = swz((u32)(m0 + g + 8) * 128 + 16 * n + 4 * q4);
        st32(base + o0, f16pk(c[n][0], c[n][1]));
        st32(base + o1, f16pk(c[n][2], c[n][3]));
    }
}
static __device__ __forceinline__ void rowsum(const float (*c)[4], float& r0, float& r1) {
    float s0 = 0.f, s1 = 0.f;
#pragma unroll
    for (int n = 0; n < 8; n++) { s0 += c[n][0] + c[n][1]; s1 += c[n][2] + c[n][3]; }
    s0 += __shfl_xor_sync(~0u, s0, 1); s0 += __shfl_xor_sync(~0u, s0, 2);
    s1 += __shfl_xor_sync(~0u, s1, 1); s1 += __shfl_xor_sync(~0u, s1, 2);
    r0 = s0; r1 = s1;
}
static __device__ __forceinline__ void rowsumsq(const float (*c)[4], float& r0, float& r1) {
    float s0 = 0.f, s1 = 0.f;
#pragma unroll
    for (int n = 0; n < 8; n++) {
        s0 += c[n][0] * c[n][0] + c[n][1] * c[n][1];
        s1 += c[n][2] * c[n][2] + c[n][3] * c[n][3];
    }
    s0 += __shfl_xor_sync(~0u, s0, 1); s0 += __shfl_xor_sync(~0u, s0, 2);
    s1 += __shfl_xor_sync(~0u, s1, 1); s1 += __shfl_xor_sync(~0u, s1, 2);
    r0 = s0; r1 = s1;
}
static __device__ __forceinline__ void stageW(const float* __restrict__ W, u32 base, int tid) {
    for (int i = tid; i < 2048; i += 512) {
        int r = i >> 5, c2 = (i & 31) * 2;
        float2 w = *(const float2*)(W + r * 64 + c2);
        u32 h, l; split2(w.x, w.y, h, l);
        u32 o = swz((u32)r * 128 + (u32)c2 * 2);
        st32(base + o, h); st32(base + LOD_W + o, l);
    }
}

// ---------------- transposes (float4, 128-wide t tiles; chunked by n) ----------------
__global__ void k_tin(const float* __restrict__ in, int n0) {
    __shared__ float tile[32][129];
    int n = n0 + (blockIdx.z >> 8), f = blockIdx.z & 255;
    int c0 = blockIdx.y << 5, t0 = blockIdx.x << 7;
    int j = threadIdx.x;
    int tr = j & 31, cr = j >> 5;
    size_t base_in = ((size_t)(n * 64 + c0) * 256 + f) * 256 + t0;
#pragma unroll
    for (int p = 0; p < 4; p++) {
        int c = cr + p * 8;
        float4 v = *(const float4*)(in + base_in + (size_t)c * 65536 + 4 * tr);
        tile[c][4 * tr] = v.x; tile[c][4 * tr + 1] = v.y;
        tile[c][4 * tr + 2] = v.z; tile[c][4 * tr + 3] = v.w;
    }
    __syncthreads();
    int cw = (j & 7) * 4, trw = j >> 3;
    size_t base_out = (size_t)(n * 256) * 16384 + (size_t)f * 64 + c0;
#pragma unroll
    for (int p = 0; p < 4; p++) {
        int t = trw + p * 32;
        float4 v = make_float4(tile[cw][t], tile[cw + 1][t], tile[cw + 2][t], tile[cw + 3][t]);
        *(float4*)(g_scratch + base_out + (size_t)(t0 + t) * 16384 + cw) = v;
    }
}
__global__ void k_tout(const float* __restrict__ in, float* __restrict__ out, int n0) {
    __shared__ float tile[32][129];
    int n = n0 + (blockIdx.z >> 8), f = blockIdx.z & 255;
    int c0 = blockIdx.y << 5, t0 = blockIdx.x << 7;
    int j = threadIdx.x;
    int cw = (j & 7) * 4, trw = j >> 3;
    size_t base_y = (size_t)(n * 256) * 16384 + (size_t)f * 64 + c0;
#pragma unroll
    for (int p = 0; p < 4; p++) {
        int t = trw + p * 32;
        float4 v = *(const float4*)(g_scratch + base_y + (size_t)(t0 + t) * 16384 + cw);
        tile[cw][t] = v.x; tile[cw + 1][t] = v.y; tile[cw + 2][t] = v.z; tile[cw + 3][t] = v.w;
    }
    __syncthreads();
    int tr = j & 31, cr = j >> 5;
    size_t base_o = ((size_t)(n * 64 + c0) * 256 + f) * 256 + t0;
#pragma unroll
    for (int p = 0; p < 4; p++) {
        int c = cr + p * 8;
        size_t a = base_o + (size_t)c * 65536 + 4 * tr;
        float4 r = *(const float4*)(in + a);
        r.x += tile[c][4 * tr];     r.y += tile[c][4 * tr + 1];
        r.z += tile[c][4 * tr + 2]; r.w += tile[c][4 * tr + 3];
        *(float4*)(out + a) = r;
    }
}

// ---------------- fused attention (mma.sync, 512 threads, 16 rows/warp) ----------------
__global__ void __launch_bounds__(512, 1) k_attn(
    const float* __restrict__ Wq, const float* __restrict__ bq,
    const float* __restrict__ Wk, const float* __restrict__ bk,
    const float* __restrict__ Wv, const float* __restrict__ bv,
    const float* __restrict__ g1, const float* __restrict__ b1,
    const float* __restrict__ g2, const float* __restrict__ b2,
    const float* __restrict__ Wt, const float* __restrict__ bt,
    const float* __restrict__ g3, const float* __restrict__ b3,
    const float* __restrict__ alpha, int b0)
{
    extern __shared__ char smem[];
    u32 sb = s2u(smem);
    float* wkm = (float*)(smem + R_KM);
    int tid = threadIdx.x, lane = tid & 31, wrp = tid >> 5;
    int g = lane >> 2, q4 = lane & 3, ll = lane & 15;
    int m0 = wrp * 16;
    float* xb = g_scratch + (size_t)(blockIdx.x + b0) * 16384;

    // Stage Wk (overlaps LN1's x loads)
    stageW(Wk, sb + R_WKP, tid);

    // Phase 0: LN1 (warp per row, 16 warps) -> H hi/lo tiles
    {
        float2 g1v = ((const float2*)g1)[lane];
        float2 b1v = ((const float2*)b1)[lane];
        for (int r = wrp; r < 256; r += 16) {
            float2 x = *(const float2*)(xb + r * 64 + 2 * lane);
            float s = x.x + x.y;
#pragma unroll
            for (int o = 16; o; o >>= 1) s += __shfl_xor_sync(~0u, s, o);
            float mean = s * (1.0f / 64.0f);
            float d0 = x.x - mean, d1 = x.y - mean;
            float v = d0 * d0 + d1 * d1;
#pragma unroll
            for (int o = 16; o; o >>= 1) v += __shfl_xor_sync(~0u, v, o);
            float rs = rsqrtf(v * (1.0f / 64.0f) + 1e-5f);
            u32 h, l; split2(d0 * rs * g1v.x + b1v.x, d1 * rs * g1v.y + b1v.y, h, l);
            u32 o = swz((u32)r * 128 + (u32)lane * 4);
            st32(sb + R_H + o, h); st32(sb + R_H + LOD_T + o, l);
        }
    }
    __syncthreads();

    // H A-fragments for this warp's 16 rows
    u32 hah[4][4], hal[4][4];
#pragma unroll
    for (int k = 0; k < 4; k++) {
        u32 o = swz((u32)(m0 + (lane & 15)) * 128 + (u32)k * 32 + ((lane >> 4) & 1) * 16);
        ldm4(hah[k], sb + R_H + o);
        ldm4(hal[k], sb + R_H + LOD_T + o);
    }
    __syncthreads();   // H tiles consumed -> region becomes weight storage

    // Prefetch Wv/Wq/Wt into registers (latency hidden behind K projection)
    float2 wv_r[4], wq_r[4], wt_r[4];
#pragma unroll
    for (int it = 0; it < 4; it++) {
        int i = tid + it * 512;
        int r = i >> 5, c2 = (i & 31) * 2;
        wv_r[it] = *(const float2*)(Wv + r * 64 + c2);
        wq_r[it] = *(const float2*)(Wq + r * 64 + c2);
        wt_r[it] = *(const float2*)(Wt + r * 64 + c2);
    }

    // K projection (Wk preloaded) -> K tiles + max||k||^2
    {
        float c[8][4];
#pragma unroll
        for (int n = 0; n < 8; n++) { c[n][0] = c[n][1] = c[n][2] = c[n][3] = 0.f; }
        gemm64(c, hah, hal, sb + R_WKP, LOD_W, 0, 0, ll);
        addbias(c, bk, q4);
        float a0, a1; rowsumsq(c, a0, a1);
        float kmx = fmaxf(a0, a1);
#pragma unroll
        for (int o = 16; o; o >>= 1) kmx = fmaxf(kmx, __shfl_xor_sync(~0u, kmx, o));
        if (lane == 0) wkm[wrp] = kmx;
        cstore16(c, sb + R_K, m0, lane);
    }
    // Store prefetched weights into the dead H region
#pragma unroll
    for (int it = 0; it < 4; it++) {
        int i = tid + it * 512;
        int r = i >> 5, c2 = (i & 31) * 2;
        u32 o = swz((u32)r * 128 + (u32)c2 * 2);
        u32 h, l;
        split2(wv_r[it].x, wv_r[it].y, h, l); st32(sb + R_WV + o, h); st32(sb + R_WV + LOD_W + o, l);
        split2(wq_r[it].x, wq_r[it].y, h, l); st32(sb + R_WQ + o, h); st32(sb + R_WQ + LOD_W + o, l);
        split2(wt_r[it].x, wt_r[it].y, h, l); st32(sb + R_WT + o, h); st32(sb + R_WT + LOD_W + o, l);
    }
    __syncthreads();

    // V projection -> V tile (hi only; 2-term)
    {
        float c[8][4];
#pragma unroll
        for (int n = 0; n < 8; n++) { c[n][0] = c[n][1] = c[n][2] = c[n][3] = 0.f; }
        gemm64_2(c, hah, sb + R_WV, LOD_W, 0, 0, ll);
        addbias(c, bv, q4);
        cstore16_hi(c, sb + R_V, m0, lane);
    }
    // Q projection -> A-fragments + ||q||
    u32 qah[4][4], qal[4][4];
    float qn0, qn1;
    {
        float c[8][4];
#pragma unroll
        for (int n = 0; n < 8; n++) { c[n][0] = c[n][1] = c[n][2] = c[n][3] = 0.f; }
        gemm64(c, hah, hal, sb + R_WQ, LOD_W, 0, 0, ll);
        addbias(c, bq, q4);
        float a0, a1; rowsumsq(c, a0, a1);
        qn0 = sqrtf(a0); qn1 = sqrtf(a1);
        c2a(c, qah, qal);
    }
    __syncthreads();   // K, V tiles + wkm complete

    float kmax;
    {
        float m = wkm[0];
#pragma unroll
        for (int i = 1; i < 16; i++) m = fmaxf(m, wkm[i]);
        kmax = sqrtf(m);
    }
    // Flash loop (sync-free): safe max = ||q||*kmax/8 - 8
    float mr0 = qn0 * kmax * 0.125f - 8.0f;
    float mr1 = qn1 * kmax * 0.125f - 8.0f;
    float ov[8][4];
#pragma unroll
    for (int n = 0; n < 8; n++) { ov[n][0] = ov[n][1] = ov[n][2] = ov[n][3] = 0.f; }

#pragma unroll 1
    for (int sc = 0; sc < 4; sc++) {
        float s[8][4];
#pragma unroll
        for (int n = 0; n < 8; n++) { s[n][0] = s[n][1] = s[n][2] = s[n][3] = 0.f; }
        gemm64(s, qah, qal, sb + R_K, LOD_T, sc * 64, 0, ll);
#pragma unroll
        for (int n = 0; n < 8; n++) {
            s[n][0] = __expf(fmaf(s[n][0], 0.125f, -mr0));
            s[n][1] = __expf(fmaf(s[n][1], 0.125f, -mr0));
            s[n][2] = __expf(fmaf(s[n][2], 0.125f, -mr1));
            s[n][3] = __expf(fmaf(s[n][3], 0.125f, -mr1));
        }
        u32 ph[4][4];
        c2a_hi(s, ph);
        gemm64_1t(ov, ph, sb + R_V, sc * 64, ll);
    }

    // Epilogue: LN2 (regs) -> Wt GEMM (2-term) -> LN3 + PReLU -> scratch (coalesced)
    float alv = __ldg(alpha);
    {
        float s0v, s1v, ss0, ss1;
        rowsum(ov, s0v, s1v);
        rowsumsq(ov, ss0, ss1);
        float mu0 = s0v * (1.0f / 64.0f), mu1 = s1v * (1.0f / 64.0f);
        float rs0 = rsqrtf(fmaxf(ss0 * (1.0f / 64.0f) - mu0 * mu0, 0.f) + 1e-12f);
        float rs1 = rsqrtf(fmaxf(ss1 * (1.0f / 64.0f) - mu1 * mu1, 0.f) + 1e-12f);
#pragma unroll
        for (int n = 0; n < 8; n++) {
            int c0i = 8 * n + 2 * q4;
            float2 g2v = *(const float2*)(g2 + c0i);
            float2 b2v = *(const float2*)(b2 + c0i);
            ov[n][0] = (ov[n][0] - mu0) * rs0 * g2v.x + b2v.x;
            ov[n][1] = (ov[n][1] - mu0) * rs0 * g2v.y + b2v.y;
            ov[n][2] = (ov[n][2] - mu1) * rs1 * g2v.x + b2v.x;
            ov[n][3] = (ov[n][3] - mu1) * rs1 * g2v.y + b2v.y;
        }
    }
    {
        u32 yh[4][4];
        c2a_hi(ov, yh);
        float y[8][4];
#pragma unroll
        for (int n = 0; n < 8; n++) { y[n][0] = y[n][1] = y[n][2] = y[n][3] = 0.f; }
        gemm64_2(y, yh, sb + R_WT, LOD_W, 0, 0, ll);
        addbias(y, bt, q4);
        float s0v, s1v, ss0, ss1;
        rowsum(y, s0v, s1v);
        rowsumsq(y, ss0, ss1);
        float mu0 = s0v * (1.0f / 64.0f), mu1 = s1v * (1.0f / 64.0f);
        float rs0 = rsqrtf(ss0 * (1.0f / 64.0f) - mu0 * mu0 + 1e-5f);
        float rs1 = rsqrtf(ss1 * (1.0f / 64.0f) - mu1 * mu1 + 1e-5f);
#pragma unroll
        for (int n = 0; n < 8; n++) {
            int c0i = 8 * n + 2 * q4;
            float2 g3v = *(const float2*)(g3 + c0i);
            float2 b3v = *(const float2*)(b3 + c0i);
            float e0 = (y[n][0] - mu0) * rs0 * g3v.x + b3v.x; e0 = e0 >= 0.f ? e0 : alv * e0;
            float e1 = (y[n][1] - mu0) * rs0 * g3v.y + b3v.y; e1 = e1 >= 0.f ? e1 : alv * e1;
            float e2 = (y[n][2] - mu1) * rs1 * g3v.x + b3v.x; e2 = e2 >= 0.f ? e2 : alv * e2;
            float e3 = (y[n][3] - mu1) * rs1 * g3v.y + b3v.y; e3 = e3 >= 0.f ? e3 : alv * e3;
            *(float2*)(xb + (m0 + g) * 64 + c0i)     = make_float2(e0, e1);
            *(float2*)(xb + (m0 + g + 8) * 64 + c0i) = make_float2(e2, e3);
        }
    }
}

// ---------------- launch: 2-chunk pipeline (tin || attn || tout), wave-aligned ----------------
#define NCHUNK 2
extern "C" void kernel_launch(void* const* d_in, const int* in_sizes, int n_in,
                              void* d_out, int out_size) {
    (void)in_sizes; (void)n_in; (void)out_size;
    const float* inputs = (const float*)d_in[0];
    const float* Wq = (const float*)d_in[1];  const float* bq = (const float*)d_in[2];
    const float* Wk = (const float*)d_in[3];  const float* bk = (const float*)d_in[4];
    const float* Wv = (const float*)d_in[5];  const float* bv = (const float*)d_in[6];
    const float* g1 = (const float*)d_in[7];  const float* b1 = (const float*)d_in[8];
    const float* g2 = (const float*)d_in[9];  const float* b2 = (const float*)d_in[10];
    const float* Wt = (const float*)d_in[11]; const float* bt = (const float*)d_in[12];
    const float* g3 = (const float*)d_in[13]; const float* b3 = (const float*)d_in[14];
    const float* alpha = (const float*)d_in[15];
    float* out = (float*)d_out;

    static cudaStream_t sA = nullptr, sB = nullptr;
    static cudaEvent_t evT[NCHUNK], evA[NCHUNK], evRoot, evEnd;
    if (!sA) {   // first call is the (uncaptured) correctness run
        cudaStreamCreateWithFlags(&sA, cudaStreamNonBlocking);
        cudaStreamCreateWithFlags(&sB, cudaStreamNonBlocking);
        for (int i = 0; i < NCHUNK; i++) {
            cudaEventCreateWithFlags(&evT[i], cudaEventDisableTiming);
            cudaEventCreateWithFlags(&evA[i], cudaEventDisableTiming);
        }
        cudaEventCreateWithFlags(&evRoot, cudaEventDisableTiming);
        cudaEventCreateWithFlags(&evEnd, cudaEventDisableTiming);
        cudaFuncSetAttribute(k_attn, cudaFuncAttributeMaxDynamicSharedMemorySize, SMEM_BYTES);
    }

    dim3 tg(2, 2, 1024);         // per-chunk transpose grid (4 n-values, 4096 blocks)
    cudaEventRecord(evRoot, 0);
    cudaStreamWaitEvent(sA, evRoot, 0);
    for (int g = 0; g < NCHUNK; g++) {
        k_tin<<<tg, 256, 0, sA>>>(inputs, 4 * g);
        cudaEventRecord(evT[g], sA);
    }
    for (int g = 0; g < NCHUNK; g++) {
        cudaStreamWaitEvent(0, evT[g], 0);
        k_attn<<<1024, 512, SMEM_BYTES>>>(Wq, bq, Wk, bk, Wv, bv, g1, b1, g2, b2,
                                          Wt, bt, g3, b3, alpha, 1024 * g);
        cudaEventRecord(evA[g], 0);
        cudaStreamWaitEvent(sB, evA[g], 0);
        k_tout<<<tg, 256, 0, sB>>>(inputs, out, 4 * g);
    }
    cudaEventRecord(evEnd, sB);
    cudaStreamWaitEvent(0, evEnd, 0);
}

// round 14
// speedup vs baseline: 1.2263x; 1.1273x over previous
#include <cuda_runtime.h>
#include <cstdint>

typedef uint32_t u32;
#define BB 2048

// scratch per batch: 64KB = H-hi tile (32KB) + H-lo tile (32KB), later overwritten by y (fp32)
__device__ float g_scratch[(size_t)BB * 256 * 64];

// ---- smem map (bytes) ----
#define R_H   0
#define R_WV  16384
#define R_WQ  32768
#define R_WT  49152
#define R_K   65536      // K tiles hi/lo (64KB)
#define R_V   131072     // V tile hi only (32KB)
#define R_WKP 163840     // Wk hi/lo (16KB)
#define R_KM  180224     // 16 floats: per-warp max ||k||^2
#define SMEM_BYTES 180288
#define LOD_T 32768
#define LOD_W 8192

static __device__ __forceinline__ u32 s2u(const void* p) {
    u32 a;
    asm("{ .reg .u64 t; cvta.to.shared.u64 t, %1; cvt.u32.u64 %0, t; }" : "=r"(a) : "l"(p));
    return a;
}
static __device__ __forceinline__ u32 swz(u32 o) { return o ^ ((o >> 3) & 0x70); }

static __device__ __forceinline__ void ldm4(u32* r, u32 a) {
    asm volatile("ldmatrix.sync.aligned.m8n8.x4.shared.b16 {%0,%1,%2,%3},[%4];"
                 : "=r"(r[0]), "=r"(r[1]), "=r"(r[2]), "=r"(r[3]) : "r"(a));
}
static __device__ __forceinline__ void ldm2(u32* r, u32 a) {
    asm volatile("ldmatrix.sync.aligned.m8n8.x2.shared.b16 {%0,%1},[%2];"
                 : "=r"(r[0]), "=r"(r[1]) : "r"(a));
}
static __device__ __forceinline__ void ldm2t(u32* r, u32 a) {
    asm volatile("ldmatrix.sync.aligned.m8n8.x2.trans.shared.b16 {%0,%1},[%2];"
                 : "=r"(r[0]), "=r"(r[1]) : "r"(a));
}
static __device__ __forceinline__ void hmma(float* c, const u32* a, const u32* b) {
    asm volatile("mma.sync.aligned.m16n8k16.row.col.f32.f16.f16.f32 "
                 "{%0,%1,%2,%3},{%4,%5,%6,%7},{%8,%9},{%0,%1,%2,%3};"
                 : "+f"(c[0]), "+f"(c[1]), "+f"(c[2]), "+f"(c[3])
                 : "r"(a[0]), "r"(a[1]), "r"(a[2]), "r"(a[3]), "r"(b[0]), "r"(b[1]));
}
static __device__ __forceinline__ u32 f16pk(float a, float b) {   // a -> low half
    u32 r; asm("cvt.rn.f16x2.f32 %0,%1,%2;" : "=r"(r) : "f"(b), "f"(a)); return r;
}
static __device__ __forceinline__ void h2up(u32 h, float& a, float& b) {
    asm("{.reg .b16 l,hh; mov.b32 {l,hh},%2; cvt.f32.f16 %0,l; cvt.f32.f16 %1,hh;}"
        : "=f"(a), "=f"(b) : "r"(h));
}
static __device__ __forceinline__ void split2(float a, float b, u32& hi, u32& lo) {
    u32 h = f16pk(a, b); float fa, fb; h2up(h, fa, fb);
    hi = h; lo = f16pk(a - fa, b - fb);
}
static __device__ __forceinline__ void st32(u32 a, u32 v) {
    asm volatile("st.shared.b32 [%0],%1;" :: "r"(a), "r"(v) : "memory");
}

// 3-term 64-col GEMM (paired-n interleave, batched LDSM).
static __device__ __forceinline__ void gemm64(float (*c)[4],
        const u32 (*ah)[4], const u32 (*al)[4],
        u32 bbase, u32 lod, int n0, int k0, int ll) {
#pragma unroll
    for (int np = 0; np < 4; np++) {
#pragma unroll
        for (int k = 0; k < 4; k++) {
            u32 offA = (u32)(n0 + 16 * np + (ll & 7)) * 128 + (u32)(k0 + 16 * k) * 2 + ((ll >> 3) & 1) * 16;
            u32 offB = offA + 8 * 128;
            u32 aA = bbase + swz(offA), aB = bbase + swz(offB);
            u32 bhA[2], blA[2], bhB[2], blB[2];
            ldm2(bhA, aA); ldm2(bhB, aB); ldm2(blA, aA + lod); ldm2(blB, aB + lod);
            hmma(c[2 * np], ah[k], bhA); hmma(c[2 * np + 1], ah[k], bhB);
            hmma(c[2 * np], ah[k], blA); hmma(c[2 * np + 1], ah[k], blB);
            hmma(c[2 * np], al[k], bhA); hmma(c[2 * np + 1], al[k], bhB);
        }
    }
}
// 2-term variant: A hi only, B hi+lo.
static __device__ __forceinline__ void gemm64_2(float (*c)[4],
        const u32 (*ah)[4], u32 bbase, u32 lod, int n0, int k0, int ll) {
#pragma unroll
    for (int np = 0; np < 4; np++) {
#pragma unroll
        for (int k = 0; k < 4; k++) {
            u32 offA = (u32)(n0 + 16 * np + (ll & 7)) * 128 + (u32)(k0 + 16 * k) * 2 + ((ll >> 3) & 1) * 16;
            u32 offB = offA + 8 * 128;
            u32 aA = bbase + swz(offA), aB = bbase + swz(offB);
            u32 bhA[2], blA[2], bhB[2], blB[2];
            ldm2(bhA, aA); ldm2(bhB, aB); ldm2(blA, aA + lod); ldm2(blB, aB + lod);
            hmma(c[2 * np], ah[k], bhA); hmma(c[2 * np + 1], ah[k], bhB);
            hmma(c[2 * np], ah[k], blA); hmma(c[2 * np + 1], ah[k], blB);
        }
    }
}
// 1-term trans variant: A hi, B hi (AV).
static __device__ __forceinline__ void gemm64_1t(float (*c)[4],
        const u32 (*ah)[4], u32 bbase, int k0, int ll) {
#pragma unroll
    for (int np = 0; np < 4; np++) {
#pragma unroll
        for (int k = 0; k < 4; k++) {
            u32 offA = (u32)(k0 + 16 * k + ((ll >> 3) & 1) * 8 + (ll & 7)) * 128 + (u32)(32 * np);
            u32 offB = offA + 16;
            u32 bhA[2], bhB[2];
            ldm2t(bhA, bbase + swz(offA)); ldm2t(bhB, bbase + swz(offB));
            hmma(c[2 * np], ah[k], bhA); hmma(c[2 * np + 1], ah[k], bhB);
        }
    }
}
static __device__ __forceinline__ void c2a(const float (*c)[4], u32 (*fh)[4], u32 (*fl)[4]) {
#pragma unroll
    for (int kk = 0; kk < 4; kk++) {
        split2(c[2 * kk][0],     c[2 * kk][1],     fh[kk][0], fl[kk][0]);
        split2(c[2 * kk][2],     c[2 * kk][3],     fh[kk][1], fl[kk][1]);
        split2(c[2 * kk + 1][0], c[2 * kk + 1][1], fh[kk][2], fl[kk][2]);
        split2(c[2 * kk + 1][2], c[2 * kk + 1][3], fh[kk][3], fl[kk][3]);
    }
}
static __device__ __forceinline__ void c2a_hi(const float (*c)[4], u32 (*fh)[4]) {
#pragma unroll
    for (int kk = 0; kk < 4; kk++) {
        fh[kk][0] = f16pk(c[2 * kk][0],     c[2 * kk][1]);
        fh[kk][1] = f16pk(c[2 * kk][2],     c[2 * kk][3]);
        fh[kk][2] = f16pk(c[2 * kk + 1][0], c[2 * kk + 1][1]);
        fh[kk][3] = f16pk(c[2 * kk + 1][2], c[2 * kk + 1][3]);
    }
}
static __device__ __forceinline__ void addbias(float (*c)[4], const float* __restrict__ bias, int q4) {
#pragma unroll
    for (int n = 0; n < 8; n++) {
        float b0 = bias[8 * n + 2 * q4], b1 = bias[8 * n + 2 * q4 + 1];
        c[n][0] += b0; c[n][1] += b1; c[n][2] += b0; c[n][3] += b1;
    }
}
static __device__ __forceinline__ void cstore16(const float (*c)[4], u32 base, int m0, int lane) {
    int g = lane >> 2, q4 = lane & 3;
#pragma unroll
    for (int n = 0; n < 8; n++) {
        u32 o0 = swz((u32)(m0 + g) * 128 + 16 * n + 4 * q4);
        u32 o1 = swz((u32)(m0 + g + 8) * 128 + 16 * n + 4 * q4);
        u32 h0, l0, h1, l1;
        split2(c[n][0], c[n][1], h0, l0);
        split2(c[n][2], c[n][3], h1, l1);
        st32(base + o0, h0); st32(base + LOD_T + o0, l0);
        st32(base + o1, h1); st32(base + LOD_T + o1, l1);
    }
}
static __device__ __forceinline__ void cstore16_hi(const float (*c)[4], u32 base, int m0, int lane) {
    int g = lane >> 2, q4 = lane & 3;
#pragma unroll
    for (int n = 0; n < 8; n++) {
        u32 o0 = swz((u32)(m0 + g) * 128 + 16 * n + 4 * q4);
        u32 o1 = swz((u32)(m0 + g + 8) * 128 + 16 * n + 4 * q4);
        st32(base + o0, f16pk(c[n][0], c[n][1]));
        st32(base + o1, f16pk(c[n][2], c[n][3]));
    }
}
static __device__ __forceinline__ void rowsum(const float (*c)[4], float& r0, float& r1) {
    float s0 = 0.f, s1 = 0.f;
#pragma unroll
    for (int n = 0; n < 8; n++) { s0 += c[n][0] + c[n][1]; s1 += c[n][2] + c[n][3]; }
    s0 += __shfl_xor_sync(~0u, s0, 1); s0 += __shfl_xor_sync(~0u, s0, 2);
    s1 += __shfl_xor_sync(~0u, s1, 1); s1 += __shfl_xor_sync(~0u, s1, 2);
    r0 = s0; r1 = s1;
}
static __device__ __forceinline__ void rowsumsq(const float (*c)[4], float& r0, float& r1) {
    float s0 = 0.f, s1 = 0.f;
#pragma unroll
    for (int n = 0; n < 8; n++) {
        s0 += c[n][0] * c[n][0] + c[n][1] * c[n][1];
        s1 += c[n][2] * c[n][2] + c[n][3] * c[n][3];
    }
    s0 += __shfl_xor_sync(~0u, s0, 1); s0 += __shfl_xor_sync(~0u, s0, 2);
    s1 += __shfl_xor_sync(~0u, s1, 1); s1 += __shfl_xor_sync(~0u, s1, 2);
    r0 = s0; r1 = s1;
}
static __device__ __forceinline__ void stageW(const float* __restrict__ W, u32 base, int tid) {
    for (int i = tid; i < 2048; i += 512) {
        int r = i >> 5, c2 = (i & 31) * 2;
        float2 w = *(const float2*)(W + r * 64 + c2);
        u32 h, l; split2(w.x, w.y, h, l);
        u32 o = swz((u32)r * 128 + (u32)c2 * 2);
        st32(base + o, h); st32(base + LOD_W + o, l);
    }
}

// ---------------- k_tin: load + LN1 + f16 hi/lo split -> swizzled H tiles in scratch ----------
// grid (T/128=2, nchunk*256), block 256. tile = 128t x 64c.
__global__ void k_tin(const float* __restrict__ in,
                      const float* __restrict__ g1, const float* __restrict__ b1, int n0) {
    __shared__ float tile[128][68];
    int zz = blockIdx.y;
    int n = n0 + (zz >> 8), f = zz & 255;
    int t0 = blockIdx.x << 7;
    int j = threadIdx.x;
    size_t base_in = ((size_t)(n * 64) * 256 + f) * 256 + t0;   // + c*65536 + t
#pragma unroll
    for (int it = 0; it < 8; it++) {
        int idx = j + it * 256;
        int c = idx >> 5, tq = idx & 31;
        float4 v = *(const float4*)(in + base_in + (size_t)c * 65536 + 4 * tq);
        tile[4 * tq + 0][c] = v.x; tile[4 * tq + 1][c] = v.y;
        tile[4 * tq + 2][c] = v.z; tile[4 * tq + 3][c] = v.w;
    }
    __syncthreads();
    int lane = j & 31, wrp = j >> 5;
    float2 g1v = ((const float2*)g1)[lane];
    float2 b1v = ((const float2*)b1)[lane];
    u32 wo = swz((u32)f * 128 + (u32)lane * 4);
#pragma unroll
    for (int i = 0; i < 16; i++) {
        int tt = wrp * 16 + i;
        float2 x = *(const float2*)(&tile[tt][2 * lane]);
        float s = x.x + x.y;
#pragma unroll
        for (int o = 16; o; o >>= 1) s += __shfl_xor_sync(~0u, s, o);
        float mean = s * (1.0f / 64.0f);
        float d0 = x.x - mean, d1 = x.y - mean;
        float v = d0 * d0 + d1 * d1;
#pragma unroll
        for (int o = 16; o; o >>= 1) v += __shfl_xor_sync(~0u, v, o);
        float rs = rsqrtf(v * (1.0f / 64.0f) + 1e-5f);
        u32 h, l; split2(d0 * rs * g1v.x + b1v.x, d1 * rs * g1v.y + b1v.y, h, l);
        char* gb = (char*)g_scratch + (size_t)(n * 256 + t0 + tt) * 65536;
        *(u32*)(gb + wo) = h;
        *(u32*)(gb + 32768 + wo) = l;
    }
}
// ---------------- k_tout (unchanged) ----------------
__global__ void k_tout(const float* __restrict__ in, float* __restrict__ out, int n0) {
    __shared__ float tile[32][129];
    int n = n0 + (blockIdx.z >> 8), f = blockIdx.z & 255;
    int c0 = blockIdx.y << 5, t0 = blockIdx.x << 7;
    int j = threadIdx.x;
    int cw = (j & 7) * 4, trw = j >> 3;
    size_t base_y = (size_t)(n * 256) * 16384 + (size_t)f * 64 + c0;
#pragma unroll
    for (int p = 0; p < 4; p++) {
        int t = trw + p * 32;
        float4 v = *(const float4*)(g_scratch + base_y + (size_t)(t0 + t) * 16384 + cw);
        tile[cw][t] = v.x; tile[cw + 1][t] = v.y; tile[cw + 2][t] = v.z; tile[cw + 3][t] = v.w;
    }
    __syncthreads();
    int tr = j & 31, cr = j >> 5;
    size_t base_o = ((size_t)(n * 64 + c0) * 256 + f) * 256 + t0;
#pragma unroll
    for (int p = 0; p < 4; p++) {
        int c = cr + p * 8;
        size_t a = base_o + (size_t)c * 65536 + 4 * tr;
        float4 r = *(const float4*)(in + a);
        r.x += tile[c][4 * tr];     r.y += tile[c][4 * tr + 1];
        r.z += tile[c][4 * tr + 2]; r.w += tile[c][4 * tr + 3];
        *(float4*)(out + a) = r;
    }
}

// ---------------- fused attention (mma.sync, 512 threads, 16 rows/warp) ----------------
__global__ void __launch_bounds__(512, 1) k_attn(
    const float* __restrict__ Wq, const float* __restrict__ bq,
    const float* __restrict__ Wk, const float* __restrict__ bk,
    const float* __restrict__ Wv, const float* __restrict__ bv,
    const float* __restrict__ g2, const float* __restrict__ b2,
    const float* __restrict__ Wt, const float* __restrict__ bt,
    const float* __restrict__ g3, const float* __restrict__ b3,
    const float* __restrict__ alpha, int b0)
{
    extern __shared__ char smem[];
    u32 sb = s2u(smem);
    float* wkm = (float*)(smem + R_KM);
    int tid = threadIdx.x, lane = tid & 31, wrp = tid >> 5;
    int g = lane >> 2, q4 = lane & 3, ll = lane & 15;
    int m0 = wrp * 16;
    float* xb = g_scratch + (size_t)(blockIdx.x + b0) * 16384;

    // Stage Wk; copy pre-LN'd, pre-split H tiles from scratch (coalesced)
    stageW(Wk, sb + R_WKP, tid);
    {
        const float4* hp = (const float4*)xb;
        float4* hs = (float4*)(smem + R_H);
#pragma unroll
        for (int it = 0; it < 8; it++) hs[tid + it * 512] = hp[tid + it * 512];
    }
    __syncthreads();

    // H A-fragments for this warp's 16 rows
    u32 hah[4][4], hal[4][4];
#pragma unroll
    for (int k = 0; k < 4; k++) {
        u32 o = swz((u32)(m0 + (lane & 15)) * 128 + (u32)k * 32 + ((lane >> 4) & 1) * 16);
        ldm4(hah[k], sb + R_H + o);
        ldm4(hal[k], sb + R_H + LOD_T + o);
    }
    __syncthreads();   // H tiles consumed -> region becomes weight storage

    // Prefetch Wv/Wq/Wt into registers (latency hidden behind K projection)
    float2 wv_r[4], wq_r[4], wt_r[4];
#pragma unroll
    for (int it = 0; it < 4; it++) {
        int i = tid + it * 512;
        int r = i >> 5, c2 = (i & 31) * 2;
        wv_r[it] = *(const float2*)(Wv + r * 64 + c2);
        wq_r[it] = *(const float2*)(Wq + r * 64 + c2);
        wt_r[it] = *(const float2*)(Wt + r * 64 + c2);
    }

    // K projection (Wk preloaded) -> K tiles + max||k||^2
    {
        float c[8][4];
#pragma unroll
        for (int n = 0; n < 8; n++) { c[n][0] = c[n][1] = c[n][2] = c[n][3] = 0.f; }
        gemm64(c, hah, hal, sb + R_WKP, LOD_W, 0, 0, ll);
        addbias(c, bk, q4);
        float a0, a1; rowsumsq(c, a0, a1);
        float kmx = fmaxf(a0, a1);
#pragma unroll
        for (int o = 16; o; o >>= 1) kmx = fmaxf(kmx, __shfl_xor_sync(~0u, kmx, o));
        if (lane == 0) wkm[wrp] = kmx;
        cstore16(c, sb + R_K, m0, lane);
    }
    // Store prefetched weights into the dead H region
#pragma unroll
    for (int it = 0; it < 4; it++) {
        int i = tid + it * 512;
        int r = i >> 5, c2 = (i & 31) * 2;
        u32 o = swz((u32)r * 128 + (u32)c2 * 2);
        u32 h, l;
        split2(wv_r[it].x, wv_r[it].y, h, l); st32(sb + R_WV + o, h); st32(sb + R_WV + LOD_W + o, l);
        split2(wq_r[it].x, wq_r[it].y, h, l); st32(sb + R_WQ + o, h); st32(sb + R_WQ + LOD_W + o, l);
        split2(wt_r[it].x, wt_r[it].y, h, l); st32(sb + R_WT + o, h); st32(sb + R_WT + LOD_W + o, l);
    }
    __syncthreads();

    // V projection -> V tile (hi only; 2-term)
    {
        float c[8][4];
#pragma unroll
        for (int n = 0; n < 8; n++) { c[n][0] = c[n][1] = c[n][2] = c[n][3] = 0.f; }
        gemm64_2(c, hah, sb + R_WV, LOD_W, 0, 0, ll);
        addbias(c, bv, q4);
        cstore16_hi(c, sb + R_V, m0, lane);
    }
    // Q projection -> A-fragments + ||q||
    u32 qah[4][4], qal[4][4];
    float qn0, qn1;
    {
        float c[8][4];
#pragma unroll
        for (int n = 0; n < 8; n++) { c[n][0] = c[n][1] = c[n][2] = c[n][3] = 0.f; }
        gemm64(c, hah, hal, sb + R_WQ, LOD_W, 0, 0, ll);
        addbias(c, bq, q4);
        float a0, a1; rowsumsq(c, a0, a1);
        qn0 = sqrtf(a0); qn1 = sqrtf(a1);
        c2a(c, qah, qal);
    }
    __syncthreads();   // K, V tiles + wkm complete

    float kmax;
    {
        float m = wkm[0];
#pragma unroll
        for (int i = 1; i < 16; i++) m = fmaxf(m, wkm[i]);
        kmax = sqrtf(m);
    }
    // Flash loop (sync-free): safe max = ||q||*kmax/8 - 8
    float mr0 = qn0 * kmax * 0.125f - 8.0f;
    float mr1 = qn1 * kmax * 0.125f - 8.0f;
    float ov[8][4];
#pragma unroll
    for (int n = 0; n < 8; n++) { ov[n][0] = ov[n][1] = ov[n][2] = ov[n][3] = 0.f; }

#pragma unroll 1
    for (int sc = 0; sc < 4; sc++) {
        float s[8][4];
#pragma unroll
        for (int n = 0; n < 8; n++) { s[n][0] = s[n][1] = s[n][2] = s[n][3] = 0.f; }
        gemm64(s, qah, qal, sb + R_K, LOD_T, sc * 64, 0, ll);
#pragma unroll
        for (int n = 0; n < 8; n++) {
            s[n][0] = __expf(fmaf(s[n][0], 0.125f, -mr0));
            s[n][1] = __expf(fmaf(s[n][1], 0.125f, -mr0));
            s[n][2] = __expf(fmaf(s[n][2], 0.125f, -mr1));
            s[n][3] = __expf(fmaf(s[n][3], 0.125f, -mr1));
        }
        u32 ph[4][4];
        c2a_hi(s, ph);
        gemm64_1t(ov, ph, sb + R_V, sc * 64, ll);
    }

    // Epilogue: LN2 (regs) -> Wt GEMM (2-term) -> LN3 + PReLU -> scratch (coalesced)
    float alv = __ldg(alpha);
    {
        float s0v, s1v, ss0, ss1;
        rowsum(ov, s0v, s1v);
        rowsumsq(ov, ss0, ss1);
        float mu0 = s0v * (1.0f / 64.0f), mu1 = s1v * (1.0f / 64.0f);
        float rs0 = rsqrtf(fmaxf(ss0 * (1.0f / 64.0f) - mu0 * mu0, 0.f) + 1e-12f);
        float rs1 = rsqrtf(fmaxf(ss1 * (1.0f / 64.0f) - mu1 * mu1, 0.f) + 1e-12f);
#pragma unroll
        for (int n = 0; n < 8; n++) {
            int c0i = 8 * n + 2 * q4;
            float2 g2v = *(const float2*)(g2 + c0i);
            float2 b2v = *(const float2*)(b2 + c0i);
            ov[n][0] = (ov[n][0] - mu0) * rs0 * g2v.x + b2v.x;
            ov[n][1] = (ov[n][1] - mu0) * rs0 * g2v.y + b2v.y;
            ov[n][2] = (ov[n][2] - mu1) * rs1 * g2v.x + b2v.x;
            ov[n][3] = (ov[n][3] - mu1) * rs1 * g2v.y + b2v.y;
        }
    }
    {
        u32 yh[4][4];
        c2a_hi(ov, yh);
        float y[8][4];
#pragma unroll
        for (int n = 0; n < 8; n++) { y[n][0] = y[n][1] = y[n][2] = y[n][3] = 0.f; }
        gemm64_2(y, yh, sb + R_WT, LOD_W, 0, 0, ll);
        addbias(y, bt, q4);
        float s0v, s1v, ss0, ss1;
        rowsum(y, s0v, s1v);
        rowsumsq(y, ss0, ss1);
        float mu0 = s0v * (1.0f / 64.0f), mu1 = s1v * (1.0f / 64.0f);
        float rs0 = rsqrtf(ss0 * (1.0f / 64.0f) - mu0 * mu0 + 1e-5f);
        float rs1 = rsqrtf(ss1 * (1.0f / 64.0f) - mu1 * mu1 + 1e-5f);
#pragma unroll
        for (int n = 0; n < 8; n++) {
            int c0i = 8 * n + 2 * q4;
            float2 g3v = *(const float2*)(g3 + c0i);
            float2 b3v = *(const float2*)(b3 + c0i);
            float e0 = (y[n][0] - mu0) * rs0 * g3v.x + b3v.x; e0 = e0 >= 0.f ? e0 : alv * e0;
            float e1 = (y[n][1] - mu0) * rs0 * g3v.y + b3v.y; e1 = e1 >= 0.f ? e1 : alv * e1;
            float e2 = (y[n][2] - mu1) * rs1 * g3v.x + b3v.x; e2 = e2 >= 0.f ? e2 : alv * e2;
            float e3 = (y[n][3] - mu1) * rs1 * g3v.y + b3v.y; e3 = e3 >= 0.f ? e3 : alv * e3;
            *(float2*)(xb + (m0 + g) * 64 + c0i)     = make_float2(e0, e1);
            *(float2*)(xb + (m0 + g + 8) * 64 + c0i) = make_float2(e2, e3);
        }
    }
}

// ---------------- launch: 2-chunk pipeline (tin || attn || tout), wave-aligned ----------------
#define NCHUNK 2
extern "C" void kernel_launch(void* const* d_in, const int* in_sizes, int n_in,
                              void* d_out, int out_size) {
    (void)in_sizes; (void)n_in; (void)out_size;
    const float* inputs = (const float*)d_in[0];
    const float* Wq = (const float*)d_in[1];  const float* bq = (const float*)d_in[2];
    const float* Wk = (const float*)d_in[3];  const float* bk = (const float*)d_in[4];
    const float* Wv = (const float*)d_in[5];  const float* bv = (const float*)d_in[6];
    const float* g1 = (const float*)d_in[7];  const float* b1 = (const float*)d_in[8];
    const float* g2 = (const float*)d_in[9];  const float* b2 = (const float*)d_in[10];
    const float* Wt = (const float*)d_in[11]; const float* bt = (const float*)d_in[12];
    const float* g3 = (const float*)d_in[13]; const float* b3 = (const float*)d_in[14];
    const float* alpha = (const float*)d_in[15];
    float* out = (float*)d_out;

    static cudaStream_t sA = nullptr, sB = nullptr;
    static cudaEvent_t evT[NCHUNK], evA[NCHUNK], evRoot, evEnd;
    if (!sA) {   // first call is the (uncaptured) correctness run
        cudaStreamCreateWithFlags(&sA, cudaStreamNonBlocking);
        cudaStreamCreateWithFlags(&sB, cudaStreamNonBlocking);
        for (int i = 0; i < NCHUNK; i++) {
            cudaEventCreateWithFlags(&evT[i], cudaEventDisableTiming);
            cudaEventCreateWithFlags(&evA[i], cudaEventDisableTiming);
        }
        cudaEventCreateWithFlags(&evRoot, cudaEventDisableTiming);
        cudaEventCreateWithFlags(&evEnd, cudaEventDisableTiming);
        cudaFuncSetAttribute(k_attn, cudaFuncAttributeMaxDynamicSharedMemorySize, SMEM_BYTES);
    }

    dim3 tgi(2, 1024);           // per-chunk tin grid (4 n-values)
    dim3 tgo(2, 2, 1024);        // per-chunk tout grid
    cudaEventRecord(evRoot, 0);
    cudaStreamWaitEvent(sA, evRoot, 0);
    for (int g = 0; g < NCHUNK; g++) {
        k_tin<<<tgi, 256, 0, sA>>>(inputs, g1, b1, 4 * g);
        cudaEventRecord(evT[g], sA);
    }
    for (int g = 0; g < NCHUNK; g++) {
        cudaStreamWaitEvent(0, evT[g], 0);
        k_attn<<<1024, 512, SMEM_BYTES>>>(Wq, bq, Wk, bk, Wv, bv, g2, b2,
                                          Wt, bt, g3, b3, alpha, 1024 * g);
        cudaEventRecord(evA[g], 0);
        cudaStreamWaitEvent(sB, evA[g], 0);
        k_tout<<<tgo, 256, 0, sB>>>(inputs, out, 4 * g);
    }
    cudaEventRecord(evEnd, sB);
    cudaStreamWaitEvent(0, evEnd, 0);
}

// round 15
// speedup vs baseline: 1.3779x; 1.1236x over previous
#include <cuda_runtime.h>
#include <cstdint>

typedef uint32_t u32;
#define BB 2048

// scratch per batch: 64KB = H-hi tile (32KB) + H-lo tile (32KB), later overwritten by y (fp32)
__device__ float g_scratch[(size_t)BB * 256 * 64];

// ---- smem map (bytes) ----
#define R_H   0
#define R_WV  16384
#define R_WQ  32768
#define R_WT  49152
#define R_K   65536      // K tiles hi/lo (64KB)
#define R_V   131072     // V tile hi only (32KB)
#define R_WKP 163840     // Wk hi/lo (16KB)
#define R_KM  180224     // 16 floats: per-warp max ||k||^2
#define SMEM_BYTES 180288
#define LOD_T 32768
#define LOD_W 8192

static __device__ __forceinline__ u32 s2u(const void* p) {
    u32 a;
    asm("{ .reg .u64 t; cvta.to.shared.u64 t, %1; cvt.u32.u64 %0, t; }" : "=r"(a) : "l"(p));
    return a;
}
static __device__ __forceinline__ u32 swz(u32 o) { return o ^ ((o >> 3) & 0x70); }

static __device__ __forceinline__ void ldm4(u32* r, u32 a) {
    asm volatile("ldmatrix.sync.aligned.m8n8.x4.shared.b16 {%0,%1,%2,%3},[%4];"
                 : "=r"(r[0]), "=r"(r[1]), "=r"(r[2]), "=r"(r[3]) : "r"(a));
}
static __device__ __forceinline__ void ldm2(u32* r, u32 a) {
    asm volatile("ldmatrix.sync.aligned.m8n8.x2.shared.b16 {%0,%1},[%2];"
                 : "=r"(r[0]), "=r"(r[1]) : "r"(a));
}
static __device__ __forceinline__ void ldm2t(u32* r, u32 a) {
    asm volatile("ldmatrix.sync.aligned.m8n8.x2.trans.shared.b16 {%0,%1},[%2];"
                 : "=r"(r[0]), "=r"(r[1]) : "r"(a));
}
static __device__ __forceinline__ void hmma(float* c, const u32* a, const u32* b) {
    asm volatile("mma.sync.aligned.m16n8k16.row.col.f32.f16.f16.f32 "
                 "{%0,%1,%2,%3},{%4,%5,%6,%7},{%8,%9},{%0,%1,%2,%3};"
                 : "+f"(c[0]), "+f"(c[1]), "+f"(c[2]), "+f"(c[3])
                 : "r"(a[0]), "r"(a[1]), "r"(a[2]), "r"(a[3]), "r"(b[0]), "r"(b[1]));
}
static __device__ __forceinline__ u32 f16pk(float a, float b) {   // a -> low half
    u32 r; asm("cvt.rn.f16x2.f32 %0,%1,%2;" : "=r"(r) : "f"(b), "f"(a)); return r;
}
static __device__ __forceinline__ void h2up(u32 h, float& a, float& b) {
    asm("{.reg .b16 l,hh; mov.b32 {l,hh},%2; cvt.f32.f16 %0,l; cvt.f32.f16 %1,hh;}"
        : "=f"(a), "=f"(b) : "r"(h));
}
static __device__ __forceinline__ void split2(float a, float b, u32& hi, u32& lo) {
    u32 h = f16pk(a, b); float fa, fb; h2up(h, fa, fb);
    hi = h; lo = f16pk(a - fa, b - fb);
}
static __device__ __forceinline__ void st32(u32 a, u32 v) {
    asm volatile("st.shared.b32 [%0],%1;" :: "r"(a), "r"(v) : "memory");
}

// 3-term 64-col GEMM (paired-n interleave, batched LDSM).
static __device__ __forceinline__ void gemm64(float (*c)[4],
        const u32 (*ah)[4], const u32 (*al)[4],
        u32 bbase, u32 lod, int n0, int k0, int ll) {
#pragma unroll
    for (int np = 0; np < 4; np++) {
#pragma unroll
        for (int k = 0; k < 4; k++) {
            u32 offA = (u32)(n0 + 16 * np + (ll & 7)) * 128 + (u32)(k0 + 16 * k) * 2 + ((ll >> 3) & 1) * 16;
            u32 offB = offA + 8 * 128;
            u32 aA = bbase + swz(offA), aB = bbase + swz(offB);
            u32 bhA[2], blA[2], bhB[2], blB[2];
            ldm2(bhA, aA); ldm2(bhB, aB); ldm2(blA, aA + lod); ldm2(blB, aB + lod);
            hmma(c[2 * np], ah[k], bhA); hmma(c[2 * np + 1], ah[k], bhB);
            hmma(c[2 * np], ah[k], blA); hmma(c[2 * np + 1], ah[k], blB);
            hmma(c[2 * np], al[k], bhA); hmma(c[2 * np + 1], al[k], bhB);
        }
    }
}
// 2-term variant: A hi only, B hi+lo.
static __device__ __forceinline__ void gemm64_2(float (*c)[4],
        const u32 (*ah)[4], u32 bbase, u32 lod, int n0, int k0, int ll) {
#pragma unroll
    for (int np = 0; np < 4; np++) {
#pragma unroll
        for (int k = 0; k < 4; k++) {
            u32 offA = (u32)(n0 + 16 * np + (ll & 7)) * 128 + (u32)(k0 + 16 * k) * 2 + ((ll >> 3) & 1) * 16;
            u32 offB = offA + 8 * 128;
            u32 aA = bbase + swz(offA), aB = bbase + swz(offB);
            u32 bhA[2], blA[2], bhB[2], blB[2];
            ldm2(bhA, aA); ldm2(bhB, aB); ldm2(blA, aA + lod); ldm2(blB, aB + lod);
            hmma(c[2 * np], ah[k], bhA); hmma(c[2 * np + 1], ah[k], bhB);
            hmma(c[2 * np], ah[k], blA); hmma(c[2 * np + 1], ah[k], blB);
        }
    }
}
// 1-term trans variant: A hi, B hi (AV).
static __device__ __forceinline__ void gemm64_1t(float (*c)[4],
        const u32 (*ah)[4], u32 bbase, int k0, int ll) {
#pragma unroll
    for (int np = 0; np < 4; np++) {
#pragma unroll
        for (int k = 0; k < 4; k++) {
            u32 offA = (u32)(k0 + 16 * k + ((ll >> 3) & 1) * 8 + (ll & 7)) * 128 + (u32)(32 * np);
            u32 offB = offA + 16;
            u32 bhA[2], bhB[2];
            ldm2t(bhA, bbase + swz(offA)); ldm2t(bhB, bbase + swz(offB));
            hmma(c[2 * np], ah[k], bhA); hmma(c[2 * np + 1], ah[k], bhB);
        }
    }
}
static __device__ __forceinline__ void c2a_hi(const float (*c)[4], u32 (*fh)[4]) {
#pragma unroll
    for (int kk = 0; kk < 4; kk++) {
        fh[kk][0] = f16pk(c[2 * kk][0],     c[2 * kk][1]);
        fh[kk][1] = f16pk(c[2 * kk][2],     c[2 * kk][3]);
        fh[kk][2] = f16pk(c[2 * kk + 1][0], c[2 * kk + 1][1]);
        fh[kk][3] = f16pk(c[2 * kk + 1][2], c[2 * kk + 1][3]);
    }
}
static __device__ __forceinline__ void addbias(float (*c)[4], const float* __restrict__ bias, int q4) {
#pragma unroll
    for (int n = 0; n < 8; n++) {
        float b0 = bias[8 * n + 2 * q4], b1 = bias[8 * n + 2 * q4 + 1];
        c[n][0] += b0; c[n][1] += b1; c[n][2] += b0; c[n][3] += b1;
    }
}
static __device__ __forceinline__ void cstore16(const float (*c)[4], u32 base, int m0, int lane) {
    int g = lane >> 2, q4 = lane & 3;
#pragma unroll
    for (int n = 0; n < 8; n++) {
        u32 o0 = swz((u32)(m0 + g) * 128 + 16 * n + 4 * q4);
        u32 o1 = swz((u32)(m0 + g + 8) * 128 + 16 * n + 4 * q4);
        u32 h0, l0, h1, l1;
        split2(c[n][0], c[n][1], h0, l0);
        split2(c[n][2], c[n][3], h1, l1);
        st32(base + o0, h0); st32(base + LOD_T + o0, l0);
        st32(base + o1, h1); st32(base + LOD_T + o1, l1);
    }
}
static __device__ __forceinline__ void cstore16_hi(const float (*c)[4], u32 base, int m0, int lane) {
    int g = lane >> 2, q4 = lane & 3;
#pragma unroll
    for (int n = 0; n < 8; n++) {
        u32 o0 = swz((u32)(m0 + g) * 128 + 16 * n + 4 * q4);
        u32 o1 = swz((u32)(m0 + g + 8) * 128 + 16 * n + 4 * q4);
        st32(base + o0, f16pk(c[n][0], c[n][1]));
        st32(base + o1, f16pk(c[n][2], c[n][3]));
    }
}
static __device__ __forceinline__ void rowsum(const float (*c)[4], float& r0, float& r1) {
    float s0 = 0.f, s1 = 0.f;
#pragma unroll
    for (int n = 0; n < 8; n++) { s0 += c[n][0] + c[n][1]; s1 += c[n][2] + c[n][3]; }
    s0 += __shfl_xor_sync(~0u, s0, 1); s0 += __shfl_xor_sync(~0u, s0, 2);
    s1 += __shfl_xor_sync(~0u, s1, 1); s1 += __shfl_xor_sync(~0u, s1, 2);
    r0 = s0; r1 = s1;
}
static __device__ __forceinline__ void rowsumsq(const float (*c)[4], float& r0, float& r1) {
    float s0 = 0.f, s1 = 0.f;
#pragma unroll
    for (int n = 0; n < 8; n++) {
        s0 += c[n][0] * c[n][0] + c[n][1] * c[n][1];
        s1 += c[n][2] * c[n][2] + c[n][3] * c[n][3];
    }
    s0 += __shfl_xor_sync(~0u, s0, 1); s0 += __shfl_xor_sync(~0u, s0, 2);
    s1 += __shfl_xor_sync(~0u, s1, 1); s1 += __shfl_xor_sync(~0u, s1, 2);
    r0 = s0; r1 = s1;
}
static __device__ __forceinline__ void stageW(const float* __restrict__ W, u32 base, int tid) {
    for (int i = tid; i < 2048; i += 512) {
        int r = i >> 5, c2 = (i & 31) * 2;
        float2 w = *(const float2*)(W + r * 64 + c2);
        u32 h, l; split2(w.x, w.y, h, l);
        u32 o = swz((u32)r * 128 + (u32)c2 * 2);
        st32(base + o, h); st32(base + LOD_W + o, l);
    }
}

// ---------------- k_tin: load + LN1 + f16 hi/lo split -> swizzled H tiles in scratch ----------
__global__ void k_tin(const float* __restrict__ in,
                      const float* __restrict__ g1, const float* __restrict__ b1, int n0) {
    __shared__ float tile[128][68];
    int zz = blockIdx.y;
    int n = n0 + (zz >> 8), f = zz & 255;
    int t0 = blockIdx.x << 7;
    int j = threadIdx.x;
    size_t base_in = ((size_t)(n * 64) * 256 + f) * 256 + t0;
#pragma unroll
    for (int it = 0; it < 8; it++) {
        int idx = j + it * 256;
        int c = idx >> 5, tq = idx & 31;
        float4 v = *(const float4*)(in + base_in + (size_t)c * 65536 + 4 * tq);
        tile[4 * tq + 0][c] = v.x; tile[4 * tq + 1][c] = v.y;
        tile[4 * tq + 2][c] = v.z; tile[4 * tq + 3][c] = v.w;
    }
    __syncthreads();
    int lane = j & 31, wrp = j >> 5;
    float2 g1v = ((const float2*)g1)[lane];
    float2 b1v = ((const float2*)b1)[lane];
    u32 wo = swz((u32)f * 128 + (u32)lane * 4);
#pragma unroll
    for (int i = 0; i < 16; i++) {
        int tt = wrp * 16 + i;
        float2 x = *(const float2*)(&tile[tt][2 * lane]);
        float s = x.x + x.y;
#pragma unroll
        for (int o = 16; o; o >>= 1) s += __shfl_xor_sync(~0u, s, o);
        float mean = s * (1.0f / 64.0f);
        float d0 = x.x - mean, d1 = x.y - mean;
        float v = d0 * d0 + d1 * d1;
#pragma unroll
        for (int o = 16; o; o >>= 1) v += __shfl_xor_sync(~0u, v, o);
        float rs = rsqrtf(v * (1.0f / 64.0f) + 1e-5f);
        u32 h, l; split2(d0 * rs * g1v.x + b1v.x, d1 * rs * g1v.y + b1v.y, h, l);
        char* gb = (char*)g_scratch + (size_t)(n * 256 + t0 + tt) * 65536;
        *(u32*)(gb + wo) = h;
        *(u32*)(gb + 32768 + wo) = l;
    }
}
// ---------------- k_tout ----------------
__global__ void k_tout(const float* __restrict__ in, float* __restrict__ out, int n0) {
    __shared__ float tile[32][129];
    int n = n0 + (blockIdx.z >> 8), f = blockIdx.z & 255;
    int c0 = blockIdx.y << 5, t0 = blockIdx.x << 7;
    int j = threadIdx.x;
    int cw = (j & 7) * 4, trw = j >> 3;
    size_t base_y = (size_t)(n * 256) * 16384 + (size_t)f * 64 + c0;
#pragma unroll
    for (int p = 0; p < 4; p++) {
        int t = trw + p * 32;
        float4 v = *(const float4*)(g_scratch + base_y + (size_t)(t0 + t) * 16384 + cw);
        tile[cw][t] = v.x; tile[cw + 1][t] = v.y; tile[cw + 2][t] = v.z; tile[cw + 3][t] = v.w;
    }
    __syncthreads();
    int tr = j & 31, cr = j >> 5;
    size_t base_o = ((size_t)(n * 64 + c0) * 256 + f) * 256 + t0;
#pragma unroll
    for (int p = 0; p < 4; p++) {
        int c = cr + p * 8;
        size_t a = base_o + (size_t)c * 65536 + 4 * tr;
        float4 r = *(const float4*)(in + a);
        r.x += tile[c][4 * tr];     r.y += tile[c][4 * tr + 1];
        r.z += tile[c][4 * tr + 2]; r.w += tile[c][4 * tr + 3];
        *(float4*)(out + a) = r;
    }
}

// ---------------- fused attention (mma.sync, 512 threads, 16 rows/warp) ----------------
__global__ void __launch_bounds__(512, 1) k_attn(
    const float* __restrict__ Wq, const float* __restrict__ bq,
    const float* __restrict__ Wk, const float* __restrict__ bk,
    const float* __restrict__ Wv, const float* __restrict__ bv,
    const float* __restrict__ g2, const float* __restrict__ b2,
    const float* __restrict__ Wt, const float* __restrict__ bt,
    const float* __restrict__ g3, const float* __restrict__ b3,
    const float* __restrict__ alpha, int b0)
{
    extern __shared__ char smem[];
    u32 sb = s2u(smem);
    float* wkm = (float*)(smem + R_KM);
    int tid = threadIdx.x, lane = tid & 31, wrp = tid >> 5;
    int g = lane >> 2, q4 = lane & 3, ll = lane & 15;
    int m0 = wrp * 16;
    float* xb = g_scratch + (size_t)(blockIdx.x + b0) * 16384;

    // Stage Wk; copy pre-LN'd, pre-split H tiles from scratch (coalesced)
    stageW(Wk, sb + R_WKP, tid);
    {
        const float4* hp = (const float4*)xb;
        float4* hs = (float4*)(smem + R_H);
#pragma unroll
        for (int it = 0; it < 8; it++) hs[tid + it * 512] = hp[tid + it * 512];
    }
    __syncthreads();

    // H A-fragments for this warp's 16 rows
    u32 hah[4][4], hal[4][4];
#pragma unroll
    for (int k = 0; k < 4; k++) {
        u32 o = swz((u32)(m0 + (lane & 15)) * 128 + (u32)k * 32 + ((lane >> 4) & 1) * 16);
        ldm4(hah[k], sb + R_H + o);
        ldm4(hal[k], sb + R_H + LOD_T + o);
    }
    __syncthreads();   // H tiles consumed -> region becomes weight storage

    // Prefetch Wv/Wq/Wt into registers (latency hidden behind K projection)
    float2 wv_r[4], wq_r[4], wt_r[4];
#pragma unroll
    for (int it = 0; it < 4; it++) {
        int i = tid + it * 512;
        int r = i >> 5, c2 = (i & 31) * 2;
        wv_r[it] = *(const float2*)(Wv + r * 64 + c2);
        wq_r[it] = *(const float2*)(Wq + r * 64 + c2);
        wt_r[it] = *(const float2*)(Wt + r * 64 + c2);
    }

    // K projection (Wk preloaded, 3-term) -> K tiles hi/lo + max||k||^2
    {
        float c[8][4];
#pragma unroll
        for (int n = 0; n < 8; n++) { c[n][0] = c[n][1] = c[n][2] = c[n][3] = 0.f; }
        gemm64(c, hah, hal, sb + R_WKP, LOD_W, 0, 0, ll);
        addbias(c, bk, q4);
        float a0, a1; rowsumsq(c, a0, a1);
        float kmx = fmaxf(a0, a1);
#pragma unroll
        for (int o = 16; o; o >>= 1) kmx = fmaxf(kmx, __shfl_xor_sync(~0u, kmx, o));
        if (lane == 0) wkm[wrp] = kmx;
        cstore16(c, sb + R_K, m0, lane);
    }
    // Store prefetched weights into the dead H region
#pragma unroll
    for (int it = 0; it < 4; it++) {
        int i = tid + it * 512;
        int r = i >> 5, c2 = (i & 31) * 2;
        u32 o = swz((u32)r * 128 + (u32)c2 * 2);
        u32 h, l;
        split2(wv_r[it].x, wv_r[it].y, h, l); st32(sb + R_WV + o, h); st32(sb + R_WV + LOD_W + o, l);
        split2(wq_r[it].x, wq_r[it].y, h, l); st32(sb + R_WQ + o, h); st32(sb + R_WQ + LOD_W + o, l);
        split2(wt_r[it].x, wt_r[it].y, h, l); st32(sb + R_WT + o, h); st32(sb + R_WT + LOD_W + o, l);
    }
    __syncthreads();

    // V projection -> V tile (hi only; 2-term)
    {
        float c[8][4];
#pragma unroll
        for (int n = 0; n < 8; n++) { c[n][0] = c[n][1] = c[n][2] = c[n][3] = 0.f; }
        gemm64_2(c, hah, sb + R_WV, LOD_W, 0, 0, ll);
        addbias(c, bv, q4);
        cstore16_hi(c, sb + R_V, m0, lane);
    }
    // Q projection (2-term, hi-only output: q is f16-rounded for QKT anyway) + ||q||
    u32 qah[4][4];
    float qn0, qn1;
    {
        float c[8][4];
#pragma unroll
        for (int n = 0; n < 8; n++) { c[n][0] = c[n][1] = c[n][2] = c[n][3] = 0.f; }
        gemm64_2(c, hah, sb + R_WQ, LOD_W, 0, 0, ll);
        addbias(c, bq, q4);
        float a0, a1; rowsumsq(c, a0, a1);
        qn0 = sqrtf(a0); qn1 = sqrtf(a1);
        c2a_hi(c, qah);
    }
    __syncthreads();   // K, V tiles + wkm complete

    float kmax;
    {
        float m = wkm[0];
#pragma unroll
        for (int i = 1; i < 16; i++) m = fmaxf(m, wkm[i]);
        kmax = sqrtf(m);
    }
    // Flash loop (sync-free): safe max = ||q||*kmax/8 - 8
    float mr0 = qn0 * kmax * 0.125f - 8.0f;
    float mr1 = qn1 * kmax * 0.125f - 8.0f;
    float ov[8][4];
#pragma unroll
    for (int n = 0; n < 8; n++) { ov[n][0] = ov[n][1] = ov[n][2] = ov[n][3] = 0.f; }

#pragma unroll 1
    for (int sc = 0; sc < 4; sc++) {
        float s[8][4];
#pragma unroll
        for (int n = 0; n < 8; n++) { s[n][0] = s[n][1] = s[n][2] = s[n][3] = 0.f; }
        gemm64_2(s, qah, sb + R_K, LOD_T, sc * 64, 0, ll);   // QKT 2-term
#pragma unroll
        for (int n = 0; n < 8; n++) {
            s[n][0] = __expf(fmaf(s[n][0], 0.125f, -mr0));
            s[n][1] = __expf(fmaf(s[n][1], 0.125f, -mr0));
            s[n][2] = __expf(fmaf(s[n][2], 0.125f, -mr1));
            s[n][3] = __expf(fmaf(s[n][3], 0.125f, -mr1));
        }
        u32 ph[4][4];
        c2a_hi(s, ph);
        gemm64_1t(ov, ph, sb + R_V, sc * 64, ll);
    }

    // Epilogue: LN2 (regs) -> Wt GEMM (2-term) -> LN3 + PReLU -> scratch (coalesced)
    float alv = __ldg(alpha);
    {
        float s0v, s1v, ss0, ss1;
        rowsum(ov, s0v, s1v);
        rowsumsq(ov, ss0, ss1);
        float mu0 = s0v * (1.0f / 64.0f), mu1 = s1v * (1.0f / 64.0f);
        float rs0 = rsqrtf(fmaxf(ss0 * (1.0f / 64.0f) - mu0 * mu0, 0.f) + 1e-12f);
        float rs1 = rsqrtf(fmaxf(ss1 * (1.0f / 64.0f) - mu1 * mu1, 0.f) + 1e-12f);
#pragma unroll
        for (int n = 0; n < 8; n++) {
            int c0i = 8 * n + 2 * q4;
            float2 g2v = *(const float2*)(g2 + c0i);
            float2 b2v = *(const float2*)(b2 + c0i);
            ov[n][0] = (ov[n][0] - mu0) * rs0 * g2v.x + b2v.x;
            ov[n][1] = (ov[n][1] - mu0) * rs0 * g2v.y + b2v.y;
            ov[n][2] = (ov[n][2] - mu1) * rs1 * g2v.x + b2v.x;
            ov[n][3] = (ov[n][3] - mu1) * rs1 * g2v.y + b2v.y;
        }
    }
    {
        u32 yh[4][4];
        c2a_hi(ov, yh);
        float y[8][4];
#pragma unroll
        for (int n = 0; n < 8; n++) { y[n][0] = y[n][1] = y[n][2] = y[n][3] = 0.f; }
        gemm64_2(y, yh, sb + R_WT, LOD_W, 0, 0, ll);
        addbias(y, bt, q4);
        float s0v, s1v, ss0, ss1;
        rowsum(y, s0v, s1v);
        rowsumsq(y, ss0, ss1);
        float mu0 = s0v * (1.0f / 64.0f), mu1 = s1v * (1.0f / 64.0f);
        float rs0 = rsqrtf(ss0 * (1.0f / 64.0f) - mu0 * mu0 + 1e-5f);
        float rs1 = rsqrtf(ss1 * (1.0f / 64.0f) - mu1 * mu1 + 1e-5f);
#pragma unroll
        for (int n = 0; n < 8; n++) {
            int c0i = 8 * n + 2 * q4;
            float2 g3v = *(const float2*)(g3 + c0i);
            float2 b3v = *(const float2*)(b3 + c0i);
            float e0 = (y[n][0] - mu0) * rs0 * g3v.x + b3v.x; e0 = e0 >= 0.f ? e0 : alv * e0;
            float e1 = (y[n][1] - mu0) * rs0 * g3v.y + b3v.y; e1 = e1 >= 0.f ? e1 : alv * e1;
            float e2 = (y[n][2] - mu1) * rs1 * g3v.x + b3v.x; e2 = e2 >= 0.f ? e2 : alv * e2;
            float e3 = (y[n][3] - mu1) * rs1 * g3v.y + b3v.y; e3 = e3 >= 0.f ? e3 : alv * e3;
            *(float2*)(xb + (m0 + g) * 64 + c0i)     = make_float2(e0, e1);
            *(float2*)(xb + (m0 + g + 8) * 64 + c0i) = make_float2(e2, e3);
        }
    }
}

// ---------------- launch: 2-chunk pipeline (tin || attn || tout), wave-aligned ----------------
#define NCHUNK 2
extern "C" void kernel_launch(void* const* d_in, const int* in_sizes, int n_in,
                              void* d_out, int out_size) {
    (void)in_sizes; (void)n_in; (void)out_size;
    const float* inputs = (const float*)d_in[0];
    const float* Wq = (const float*)d_in[1];  const float* bq = (const float*)d_in[2];
    const float* Wk = (const float*)d_in[3];  const float* bk = (const float*)d_in[4];
    const float* Wv = (const float*)d_in[5];  const float* bv = (const float*)d_in[6];
    const float* g1 = (const float*)d_in[7];  const float* b1 = (const float*)d_in[8];
    const float* g2 = (const float*)d_in[9];  const float* b2 = (const float*)d_in[10];
    const float* Wt = (const float*)d_in[11]; const float* bt = (const float*)d_in[12];
    const float* g3 = (const float*)d_in[13]; const float* b3 = (const float*)d_in[14];
    const float* alpha = (const float*)d_in[15];
    float* out = (float*)d_out;

    static cudaStream_t sA = nullptr, sB = nullptr;
    static cudaEvent_t evT[NCHUNK], evA[NCHUNK], evRoot, evEnd;
    if (!sA) {
        cudaStreamCreateWithFlags(&sA, cudaStreamNonBlocking);
        cudaStreamCreateWithFlags(&sB, cudaStreamNonBlocking);
        for (int i = 0; i < NCHUNK; i++) {
            cudaEventCreateWithFlags(&evT[i], cudaEventDisableTiming);
            cudaEventCreateWithFlags(&evA[i], cudaEventDisableTiming);
        }
        cudaEventCreateWithFlags(&evRoot, cudaEventDisableTiming);
        cudaEventCreateWithFlags(&evEnd, cudaEventDisableTiming);
        cudaFuncSetAttribute(k_attn, cudaFuncAttributeMaxDynamicSharedMemorySize, SMEM_BYTES);
    }

    dim3 tgi(2, 1024);
    dim3 tgo(2, 2, 1024);
    cudaEventRecord(evRoot, 0);
    cudaStreamWaitEvent(sA, evRoot, 0);
    for (int g = 0; g < NCHUNK; g++) {
        k_tin<<<tgi, 256, 0, sA>>>(inputs, g1, b1, 4 * g);
        cudaEventRecord(evT[g], sA);
    }
    for (int g = 0; g < NCHUNK; g++) {
        cudaStreamWaitEvent(0, evT[g], 0);
        k_attn<<<1024, 512, SMEM_BYTES>>>(Wq, bq, Wk, bk, Wv, bv, g2, b2,
                                          Wt, bt, g3, b3, alpha, 1024 * g);
        cudaEventRecord(evA[g], 0);
        cudaStreamWaitEvent(sB, evA[g], 0);
        k_tout<<<tgo, 256, 0, sB>>>(inputs, out, 4 * g);
    }
    cudaEventRecord(evEnd, sB);
    cudaStreamWaitEvent(0, evEnd, 0);
}

// round 16
// speedup vs baseline: 1.4838x; 1.0768x over previous
#include <cuda_runtime.h>
#include <cstdint>

typedef uint32_t u32;
#define BB 2048

// scratch per batch: 64KB region; H-hi f16 tile (32KB) then y fp32 (64KB, overwrites)
__device__ float g_scratch[(size_t)BB * 256 * 64];

// ---- smem map (bytes) ----
#define R_H   0          // H hi tile (32KB)
#define R_WK  32768      // weights hi @+0, lo @+8192 (16KB each)
#define R_WV  49152
#define R_WQ  65536
#define R_WT  81920
#define R_K   98304      // K tile hi only (32KB)
#define R_V   131072     // V tile hi only (32KB)
#define R_KM  163840     // 16 floats: per-warp max ||k||^2
#define SMEM_BYTES 163904
#define LOD_W 8192

static __device__ __forceinline__ u32 s2u(const void* p) {
    u32 a;
    asm("{ .reg .u64 t; cvta.to.shared.u64 t, %1; cvt.u32.u64 %0, t; }" : "=r"(a) : "l"(p));
    return a;
}
static __device__ __forceinline__ u32 swz(u32 o) { return o ^ ((o >> 3) & 0x70); }

static __device__ __forceinline__ void ldm4(u32* r, u32 a) {
    asm volatile("ldmatrix.sync.aligned.m8n8.x4.shared.b16 {%0,%1,%2,%3},[%4];"
                 : "=r"(r[0]), "=r"(r[1]), "=r"(r[2]), "=r"(r[3]) : "r"(a));
}
static __device__ __forceinline__ void ldm2(u32* r, u32 a) {
    asm volatile("ldmatrix.sync.aligned.m8n8.x2.shared.b16 {%0,%1},[%2];"
                 : "=r"(r[0]), "=r"(r[1]) : "r"(a));
}
static __device__ __forceinline__ void ldm2t(u32* r, u32 a) {
    asm volatile("ldmatrix.sync.aligned.m8n8.x2.trans.shared.b16 {%0,%1},[%2];"
                 : "=r"(r[0]), "=r"(r[1]) : "r"(a));
}
static __device__ __forceinline__ void hmma(float* c, const u32* a, const u32* b) {
    asm volatile("mma.sync.aligned.m16n8k16.row.col.f32.f16.f16.f32 "
                 "{%0,%1,%2,%3},{%4,%5,%6,%7},{%8,%9},{%0,%1,%2,%3};"
                 : "+f"(c[0]), "+f"(c[1]), "+f"(c[2]), "+f"(c[3])
                 : "r"(a[0]), "r"(a[1]), "r"(a[2]), "r"(a[3]), "r"(b[0]), "r"(b[1]));
}
static __device__ __forceinline__ u32 f16pk(float a, float b) {   // a -> low half
    u32 r; asm("cvt.rn.f16x2.f32 %0,%1,%2;" : "=r"(r) : "f"(b), "f"(a)); return r;
}
static __device__ __forceinline__ void h2up(u32 h, float& a, float& b) {
    asm("{.reg .b16 l,hh; mov.b32 {l,hh},%2; cvt.f32.f16 %0,l; cvt.f32.f16 %1,hh;}"
        : "=f"(a), "=f"(b) : "r"(h));
}
static __device__ __forceinline__ void split2(float a, float b, u32& hi, u32& lo) {
    u32 h = f16pk(a, b); float fa, fb; h2up(h, fa, fb);
    hi = h; lo = f16pk(a - fa, b - fb);
}
static __device__ __forceinline__ void st32(u32 a, u32 v) {
    asm volatile("st.shared.b32 [%0],%1;" :: "r"(a), "r"(v) : "memory");
}

// 2-term 64-col GEMM: A hi x (B hi + B lo). Paired-n, batched LDSM.
static __device__ __forceinline__ void gemm64_2(float (*c)[4],
        const u32 (*ah)[4], u32 bbase, u32 lod, int n0, int k0, int ll) {
#pragma unroll
    for (int np = 0; np < 4; np++) {
#pragma unroll
        for (int k = 0; k < 4; k++) {
            u32 offA = (u32)(n0 + 16 * np + (ll & 7)) * 128 + (u32)(k0 + 16 * k) * 2 + ((ll >> 3) & 1) * 16;
            u32 offB = offA + 8 * 128;
            u32 aA = bbase + swz(offA), aB = bbase + swz(offB);
            u32 bhA[2], blA[2], bhB[2], blB[2];
            ldm2(bhA, aA); ldm2(bhB, aB); ldm2(blA, aA + lod); ldm2(blB, aB + lod);
            hmma(c[2 * np], ah[k], bhA); hmma(c[2 * np + 1], ah[k], bhB);
            hmma(c[2 * np], ah[k], blA); hmma(c[2 * np + 1], ah[k], blB);
        }
    }
}
// 1-term non-trans: A hi x B hi (QKT on hi-only K tile).
static __device__ __forceinline__ void gemm64_1(float (*c)[4],
        const u32 (*ah)[4], u32 bbase, int n0, int k0, int ll) {
#pragma unroll
    for (int np = 0; np < 4; np++) {
#pragma unroll
        for (int k = 0; k < 4; k++) {
            u32 offA = (u32)(n0 + 16 * np + (ll & 7)) * 128 + (u32)(k0 + 16 * k) * 2 + ((ll >> 3) & 1) * 16;
            u32 offB = offA + 8 * 128;
            u32 bhA[2], bhB[2];
            ldm2(bhA, bbase + swz(offA)); ldm2(bhB, bbase + swz(offB));
            hmma(c[2 * np], ah[k], bhA); hmma(c[2 * np + 1], ah[k], bhB);
        }
    }
}
// 1-term trans: A hi x B hi (AV).
static __device__ __forceinline__ void gemm64_1t(float (*c)[4],
        const u32 (*ah)[4], u32 bbase, int k0, int ll) {
#pragma unroll
    for (int np = 0; np < 4; np++) {
#pragma unroll
        for (int k = 0; k < 4; k++) {
            u32 offA = (u32)(k0 + 16 * k + ((ll >> 3) & 1) * 8 + (ll & 7)) * 128 + (u32)(32 * np);
            u32 offB = offA + 16;
            u32 bhA[2], bhB[2];
            ldm2t(bhA, bbase + swz(offA)); ldm2t(bhB, bbase + swz(offB));
            hmma(c[2 * np], ah[k], bhA); hmma(c[2 * np + 1], ah[k], bhB);
        }
    }
}
static __device__ __forceinline__ void c2a_hi(const float (*c)[4], u32 (*fh)[4]) {
#pragma unroll
    for (int kk = 0; kk < 4; kk++) {
        fh[kk][0] = f16pk(c[2 * kk][0],     c[2 * kk][1]);
        fh[kk][1] = f16pk(c[2 * kk][2],     c[2 * kk][3]);
        fh[kk][2] = f16pk(c[2 * kk + 1][0], c[2 * kk + 1][1]);
        fh[kk][3] = f16pk(c[2 * kk + 1][2], c[2 * kk + 1][3]);
    }
}
static __device__ __forceinline__ void addbias(float (*c)[4], const float* __restrict__ bias, int q4) {
#pragma unroll
    for (int n = 0; n < 8; n++) {
        float b0 = bias[8 * n + 2 * q4], b1 = bias[8 * n + 2 * q4 + 1];
        c[n][0] += b0; c[n][1] += b1; c[n][2] += b0; c[n][3] += b1;
    }
}
static __device__ __forceinline__ void cstore16_hi(const float (*c)[4], u32 base, int m0, int lane) {
    int g = lane >> 2, q4 = lane & 3;
#pragma unroll
    for (int n = 0; n < 8; n++) {
        u32 o0 = swz((u32)(m0 + g) * 128 + 16 * n + 4 * q4);
        u32 o1 = swz((u32)(m0 + g + 8) * 128 + 16 * n + 4 * q4);
        st32(base + o0, f16pk(c[n][0], c[n][1]));
        st32(base + o1, f16pk(c[n][2], c[n][3]));
    }
}
static __device__ __forceinline__ void rowsum(const float (*c)[4], float& r0, float& r1) {
    float s0 = 0.f, s1 = 0.f;
#pragma unroll
    for (int n = 0; n < 8; n++) { s0 += c[n][0] + c[n][1]; s1 += c[n][2] + c[n][3]; }
    s0 += __shfl_xor_sync(~0u, s0, 1); s0 += __shfl_xor_sync(~0u, s0, 2);
    s1 += __shfl_xor_sync(~0u, s1, 1); s1 += __shfl_xor_sync(~0u, s1, 2);
    r0 = s0; r1 = s1;
}
static __device__ __forceinline__ void rowsumsq(const float (*c)[4], float& r0, float& r1) {
    float s0 = 0.f, s1 = 0.f;
#pragma unroll
    for (int n = 0; n < 8; n++) {
        s0 += c[n][0] * c[n][0] + c[n][1] * c[n][1];
        s1 += c[n][2] * c[n][2] + c[n][3] * c[n][3];
    }
    s0 += __shfl_xor_sync(~0u, s0, 1); s0 += __shfl_xor_sync(~0u, s0, 2);
    s1 += __shfl_xor_sync(~0u, s1, 1); s1 += __shfl_xor_sync(~0u, s1, 2);
    r0 = s0; r1 = s1;
}
static __device__ __forceinline__ void stageW(const float* __restrict__ W, u32 base, int tid) {
    for (int i = tid; i < 2048; i += 512) {
        int r = i >> 5, c2 = (i & 31) * 2;
        float2 w = *(const float2*)(W + r * 64 + c2);
        u32 h, l; split2(w.x, w.y, h, l);
        u32 o = swz((u32)r * 128 + (u32)c2 * 2);
        st32(base + o, h); st32(base + LOD_W + o, l);
    }
}

// ---------------- k_tin: load + LN1 -> f16 H-hi tile (swizzled) in scratch ----------
__global__ void k_tin(const float* __restrict__ in,
                      const float* __restrict__ g1, const float* __restrict__ b1, int n0) {
    __shared__ float tile[128][68];
    int zz = blockIdx.y;
    int n = n0 + (zz >> 8), f = zz & 255;
    int t0 = blockIdx.x << 7;
    int j = threadIdx.x;
    size_t base_in = ((size_t)(n * 64) * 256 + f) * 256 + t0;
#pragma unroll
    for (int it = 0; it < 8; it++) {
        int idx = j + it * 256;
        int c = idx >> 5, tq = idx & 31;
        float4 v = *(const float4*)(in + base_in + (size_t)c * 65536 + 4 * tq);
        tile[4 * tq + 0][c] = v.x; tile[4 * tq + 1][c] = v.y;
        tile[4 * tq + 2][c] = v.z; tile[4 * tq + 3][c] = v.w;
    }
    __syncthreads();
    int lane = j & 31, wrp = j >> 5;
    float2 g1v = ((const float2*)g1)[lane];
    float2 b1v = ((const float2*)b1)[lane];
    u32 wo = swz((u32)f * 128 + (u32)lane * 4);
#pragma unroll
    for (int i = 0; i < 16; i++) {
        int tt = wrp * 16 + i;
        float2 x = *(const float2*)(&tile[tt][2 * lane]);
        float s = x.x + x.y;
#pragma unroll
        for (int o = 16; o; o >>= 1) s += __shfl_xor_sync(~0u, s, o);
        float mean = s * (1.0f / 64.0f);
        float d0 = x.x - mean, d1 = x.y - mean;
        float v = d0 * d0 + d1 * d1;
#pragma unroll
        for (int o = 16; o; o >>= 1) v += __shfl_xor_sync(~0u, v, o);
        float rs = rsqrtf(v * (1.0f / 64.0f) + 1e-5f);
        u32 h = f16pk(d0 * rs * g1v.x + b1v.x, d1 * rs * g1v.y + b1v.y);
        char* gb = (char*)g_scratch + (size_t)(n * 256 + t0 + tt) * 65536;
        *(u32*)(gb + wo) = h;
    }
}
// ---------------- k_tout ----------------
__global__ void k_tout(const float* __restrict__ in, float* __restrict__ out, int n0) {
    __shared__ float tile[32][129];
    int n = n0 + (blockIdx.z >> 8), f = blockIdx.z & 255;
    int c0 = blockIdx.y << 5, t0 = blockIdx.x << 7;
    int j = threadIdx.x;
    int cw = (j & 7) * 4, trw = j >> 3;
    size_t base_y = (size_t)(n * 256) * 16384 + (size_t)f * 64 + c0;
#pragma unroll
    for (int p = 0; p < 4; p++) {
        int t = trw + p * 32;
        float4 v = *(const float4*)(g_scratch + base_y + (size_t)(t0 + t) * 16384 + cw);
        tile[cw][t] = v.x; tile[cw + 1][t] = v.y; tile[cw + 2][t] = v.z; tile[cw + 3][t] = v.w;
    }
    __syncthreads();
    int tr = j & 31, cr = j >> 5;
    size_t base_o = ((size_t)(n * 64 + c0) * 256 + f) * 256 + t0;
#pragma unroll
    for (int p = 0; p < 4; p++) {
        int c = cr + p * 8;
        size_t a = base_o + (size_t)c * 65536 + 4 * tr;
        float4 r = *(const float4*)(in + a);
        r.x += tile[c][4 * tr];     r.y += tile[c][4 * tr + 1];
        r.z += tile[c][4 * tr + 2]; r.w += tile[c][4 * tr + 3];
        *(float4*)(out + a) = r;
    }
}

// ---------------- fused attention (mma.sync, 512 threads, 16 rows/warp) ----------------
__global__ void __launch_bounds__(512, 1) k_attn(
    const float* __restrict__ Wq, const float* __restrict__ bq,
    const float* __restrict__ Wk, const float* __restrict__ bk,
    const float* __restrict__ Wv, const float* __restrict__ bv,
    const float* __restrict__ g2, const float* __restrict__ b2,
    const float* __restrict__ Wt, const float* __restrict__ bt,
    const float* __restrict__ g3, const float* __restrict__ b3,
    const float* __restrict__ alpha, int b0)
{
    extern __shared__ char smem[];
    u32 sb = s2u(smem);
    float* wkm = (float*)(smem + R_KM);
    int tid = threadIdx.x, lane = tid & 31, wrp = tid >> 5;
    int g = lane >> 2, q4 = lane & 3, ll = lane & 15;
    int m0 = wrp * 16;
    float* xb = g_scratch + (size_t)(blockIdx.x + b0) * 16384;

    // Prologue: stage all weights + copy H-hi tile (all coalesced), one sync.
    stageW(Wk, sb + R_WK, tid);
    stageW(Wv, sb + R_WV, tid);
    stageW(Wq, sb + R_WQ, tid);
    stageW(Wt, sb + R_WT, tid);
    {
        const float4* hp = (const float4*)xb;
        float4* hs = (float4*)(smem + R_H);
#pragma unroll
        for (int it = 0; it < 4; it++) hs[tid + it * 512] = hp[tid + it * 512];
    }
    __syncthreads();

    // H A-fragments (hi only)
    u32 hah[4][4];
#pragma unroll
    for (int k = 0; k < 4; k++) {
        u32 o = swz((u32)(m0 + (lane & 15)) * 128 + (u32)k * 32 + ((lane >> 4) & 1) * 16);
        ldm4(hah[k], sb + R_H + o);
    }

    // K projection (2-term) -> K tile hi + max||k||^2
    {
        float c[8][4];
#pragma unroll
        for (int n = 0; n < 8; n++) { c[n][0] = c[n][1] = c[n][2] = c[n][3] = 0.f; }
        gemm64_2(c, hah, sb + R_WK, LOD_W, 0, 0, ll);
        addbias(c, bk, q4);
        float a0, a1; rowsumsq(c, a0, a1);
        float kmx = fmaxf(a0, a1);
#pragma unroll
        for (int o = 16; o; o >>= 1) kmx = fmaxf(kmx, __shfl_xor_sync(~0u, kmx, o));
        if (lane == 0) wkm[wrp] = kmx;
        cstore16_hi(c, sb + R_K, m0, lane);
    }
    // V projection (2-term) -> V tile hi
    {
        float c[8][4];
#pragma unroll
        for (int n = 0; n < 8; n++) { c[n][0] = c[n][1] = c[n][2] = c[n][3] = 0.f; }
        gemm64_2(c, hah, sb + R_WV, LOD_W, 0, 0, ll);
        addbias(c, bv, q4);
        cstore16_hi(c, sb + R_V, m0, lane);
    }
    // Q projection (2-term, hi-only output) + ||q||
    u32 qah[4][4];
    float qn0, qn1;
    {
        float c[8][4];
#pragma unroll
        for (int n = 0; n < 8; n++) { c[n][0] = c[n][1] = c[n][2] = c[n][3] = 0.f; }
        gemm64_2(c, hah, sb + R_WQ, LOD_W, 0, 0, ll);
        addbias(c, bq, q4);
        float a0, a1; rowsumsq(c, a0, a1);
        qn0 = sqrtf(a0); qn1 = sqrtf(a1);
        c2a_hi(c, qah);
    }
    __syncthreads();   // K, V tiles + wkm complete

    float kmax;
    {
        float m = wkm[0];
#pragma unroll
        for (int i = 1; i < 16; i++) m = fmaxf(m, wkm[i]);
        kmax = sqrtf(m);
    }
    // Flash loop (sync-free): safe max = ||q||*kmax/8 - 8
    float mr0 = qn0 * kmax * 0.125f - 8.0f;
    float mr1 = qn1 * kmax * 0.125f - 8.0f;
    float ov[8][4];
#pragma unroll
    for (int n = 0; n < 8; n++) { ov[n][0] = ov[n][1] = ov[n][2] = ov[n][3] = 0.f; }

#pragma unroll 1
    for (int sc = 0; sc < 4; sc++) {
        float s[8][4];
#pragma unroll
        for (int n = 0; n < 8; n++) { s[n][0] = s[n][1] = s[n][2] = s[n][3] = 0.f; }
        gemm64_1(s, qah, sb + R_K, sc * 64, 0, ll);       // QKT 1-term
#pragma unroll
        for (int n = 0; n < 8; n++) {
            s[n][0] = __expf(fmaf(s[n][0], 0.125f, -mr0));
            s[n][1] = __expf(fmaf(s[n][1], 0.125f, -mr0));
            s[n][2] = __expf(fmaf(s[n][2], 0.125f, -mr1));
            s[n][3] = __expf(fmaf(s[n][3], 0.125f, -mr1));
        }
        u32 ph[4][4];
        c2a_hi(s, ph);
        gemm64_1t(ov, ph, sb + R_V, sc * 64, ll);         // AV 1-term
    }

    // Epilogue: LN2 (regs) -> Wt GEMM (2-term) -> LN3 + PReLU -> scratch (coalesced)
    float alv = __ldg(alpha);
    {
        float s0v, s1v, ss0, ss1;
        rowsum(ov, s0v, s1v);
        rowsumsq(ov, ss0, ss1);
        float mu0 = s0v * (1.0f / 64.0f), mu1 = s1v * (1.0f / 64.0f);
        float rs0 = rsqrtf(fmaxf(ss0 * (1.0f / 64.0f) - mu0 * mu0, 0.f) + 1e-12f);
        float rs1 = rsqrtf(fmaxf(ss1 * (1.0f / 64.0f) - mu1 * mu1, 0.f) + 1e-12f);
#pragma unroll
        for (int n = 0; n < 8; n++) {
            int c0i = 8 * n + 2 * q4;
            float2 g2v = *(const float2*)(g2 + c0i);
            float2 b2v = *(const float2*)(b2 + c0i);
            ov[n][0] = (ov[n][0] - mu0) * rs0 * g2v.x + b2v.x;
            ov[n][1] = (ov[n][1] - mu0) * rs0 * g2v.y + b2v.y;
            ov[n][2] = (ov[n][2] - mu1) * rs1 * g2v.x + b2v.x;
            ov[n][3] = (ov[n][3] - mu1) * rs1 * g2v.y + b2v.y;
        }
    }
    {
        u32 yh[4][4];
        c2a_hi(ov, yh);
        float y[8][4];
#pragma unroll
        for (int n = 0; n < 8; n++) { y[n][0] = y[n][1] = y[n][2] = y[n][3] = 0.f; }
        gemm64_2(y, yh, sb + R_WT, LOD_W, 0, 0, ll);
        addbias(y, bt, q4);
        float s0v, s1v, ss0, ss1;
        rowsum(y, s0v, s1v);
        rowsumsq(y, ss0, ss1);
        float mu0 = s0v * (1.0f / 64.0f), mu1 = s1v * (1.0f / 64.0f);
        float rs0 = rsqrtf(ss0 * (1.0f / 64.0f) - mu0 * mu0 + 1e-5f);
        float rs1 = rsqrtf(ss1 * (1.0f / 64.0f) - mu1 * mu1 + 1e-5f);
#pragma unroll
        for (int n = 0; n < 8; n++) {
            int c0i = 8 * n + 2 * q4;
            float2 g3v = *(const float2*)(g3 + c0i);
            float2 b3v = *(const float2*)(b3 + c0i);
            float e0 = (y[n][0] - mu0) * rs0 * g3v.x + b3v.x; e0 = e0 >= 0.f ? e0 : alv * e0;
            float e1 = (y[n][1] - mu0) * rs0 * g3v.y + b3v.y; e1 = e1 >= 0.f ? e1 : alv * e1;
            float e2 = (y[n][2] - mu1) * rs1 * g3v.x + b3v.x; e2 = e2 >= 0.f ? e2 : alv * e2;
            float e3 = (y[n][3] - mu1) * rs1 * g3v.y + b3v.y; e3 = e3 >= 0.f ? e3 : alv * e3;
            *(float2*)(xb + (m0 + g) * 64 + c0i)     = make_float2(e0, e1);
            *(float2*)(xb + (m0 + g + 8) * 64 + c0i) = make_float2(e2, e3);
        }
    }
}

// ---------------- launch: 2-chunk pipeline (tin || attn || tout), wave-aligned ----------------
#define NCHUNK 2
extern "C" void kernel_launch(void* const* d_in, const int* in_sizes, int n_in,
                              void* d_out, int out_size) {
    (void)in_sizes; (void)n_in; (void)out_size;
    const float* inputs = (const float*)d_in[0];
    const float* Wq = (const float*)d_in[1];  const float* bq = (const float*)d_in[2];
    const float* Wk = (const float*)d_in[3];  const float* bk = (const float*)d_in[4];
    const float* Wv = (const float*)d_in[5];  const float* bv = (const float*)d_in[6];
    const float* g1 = (const float*)d_in[7];  const float* b1 = (const float*)d_in[8];
    const float* g2 = (const float*)d_in[9];  const float* b2 = (const float*)d_in[10];
    const float* Wt = (const float*)d_in[11]; const float* bt = (const float*)d_in[12];
    const float* g3 = (const float*)d_in[13]; const float* b3 = (const float*)d_in[14];
    const float* alpha = (const float*)d_in[15];
    float* out = (float*)d_out;

    static cudaStream_t sA = nullptr, sB = nullptr;
    static cudaEvent_t evT[NCHUNK], evA[NCHUNK], evRoot, evEnd;
    if (!sA) {
        cudaStreamCreateWithFlags(&sA, cudaStreamNonBlocking);
        cudaStreamCreateWithFlags(&sB, cudaStreamNonBlocking);
        for (int i = 0; i < NCHUNK; i++) {
            cudaEventCreateWithFlags(&evT[i], cudaEventDisableTiming);
            cudaEventCreateWithFlags(&evA[i], cudaEventDisableTiming);
        }
        cudaEventCreateWithFlags(&evRoot, cudaEventDisableTiming);
        cudaEventCreateWithFlags(&evEnd, cudaEventDisableTiming);
        cudaFuncSetAttribute(k_attn, cudaFuncAttributeMaxDynamicSharedMemorySize, SMEM_BYTES);
    }

    dim3 tgi(2, 1024);
    dim3 tgo(2, 2, 1024);
    cudaEventRecord(evRoot, 0);
    cudaStreamWaitEvent(sA, evRoot, 0);
    for (int g = 0; g < NCHUNK; g++) {
        k_tin<<<tgi, 256, 0, sA>>>(inputs, g1, b1, 4 * g);
        cudaEventRecord(evT[g], sA);
    }
    for (int g = 0; g < NCHUNK; g++) {
        cudaStreamWaitEvent(0, evT[g], 0);
        k_attn<<<1024, 512, SMEM_BYTES>>>(Wq, bq, Wk, bk, Wv, bv, g2, b2,
                                          Wt, bt, g3, b3, alpha, 1024 * g);
        cudaEventRecord(evA[g], 0);
        cudaStreamWaitEvent(sB, evA[g], 0);
        k_tout<<<tgo, 256, 0, sB>>>(inputs, out, 4 * g);
    }
    cudaEventRecord(evEnd, sB);
    cudaStreamWaitEvent(0, evEnd, 0);
}